// round 7
// baseline (speedup 1.0000x reference)
#include <cuda_runtime.h>
#include <cstdint>

#define NN 8192
#define DD 128
#define NC 10
#define BT 128                 // tile edge
#define NB (NN / BT)           // 64 blocks per axis
#define NTILES (NB * (NB + 1) / 2)   // 2080
#define KC 32                  // k-chunk
#define NCHUNK (DD / KC)       // 4

// ---- device globals ----
__device__ float    g_x2[NN];
__device__ float    g_S[NN][NC];      // indexed by SORTED position
__device__ unsigned g_mp[NN];         // indexed by SORTED position
__device__ int      g_order[NN];
__device__ int      g_scls[NN];
__device__ float    g_sx2[NN];
__device__ int      g_cstart[NC];
__device__ int      g_count[NC];

#define FFMA2(acc, a, b) \
    asm("fma.rn.f32x2 %0, %1, %2, %0;" : "+l"(acc) : "l"(a), "l"(b))
#define PACK2(dst, f) \
    asm("mov.b64 %0, {%1, %1};" : "=l"(dst) : "r"(__float_as_uint(f)))

// ---------------------------------------------------------------------------
// Kernel 1: warp-per-row norms + zero g_S, g_mp, out
// ---------------------------------------------------------------------------
__global__ void bh_prep(const float* __restrict__ E, float* __restrict__ out)
{
    const int gw   = (blockIdx.x * blockDim.x + threadIdx.x) >> 5;
    const int lane = threadIdx.x & 31;
    if (blockIdx.x == 0 && threadIdx.x == 0) out[0] = 0.0f;
    if (gw < NN) {
        float4 v = *reinterpret_cast<const float4*>(E + (size_t)gw * DD + lane * 4);
        float s = v.x * v.x + v.y * v.y + v.z * v.z + v.w * v.w;
#pragma unroll
        for (int off = 16; off >= 1; off >>= 1)
            s += __shfl_xor_sync(0xffffffffu, s, off);
        if (lane == 0) { g_x2[gw] = s; g_mp[gw] = 0u; }
        if (lane < NC) g_S[gw][lane] = 0.f;
    }
}

// ---------------------------------------------------------------------------
// Kernel 2: counts, class starts, stable (class,index) sort -> order/cls/x2
// ---------------------------------------------------------------------------
__global__ void bh_table(const int* __restrict__ labels)
{
    __shared__ int sl[NN];
    __shared__ int cnt[NC][256];
    __shared__ int tot[NC], cst[NC];

    const int tid = threadIdx.x;
    for (int i = tid; i < NN; i += 256) sl[i] = labels[i];
    __syncthreads();

    const int base = tid * 32;
    int lc[NC];
#pragma unroll
    for (int c = 0; c < NC; c++) lc[c] = 0;
    for (int i = 0; i < 32; i++) {
        int lbl = sl[base + i];
#pragma unroll
        for (int c = 0; c < NC; c++) lc[c] += (lbl == c);
    }
#pragma unroll
    for (int c = 0; c < NC; c++) cnt[c][tid] = lc[c];
    __syncthreads();

    if (tid < NC) {
        int run = 0;
        for (int t = 0; t < 256; t++) { int tmp = cnt[tid][t]; cnt[tid][t] = run; run += tmp; }
        tot[tid] = run;
        g_count[tid] = run;
    }
    __syncthreads();
    if (tid == 0) {
        int run = 0;
        for (int c = 0; c < NC; c++) { cst[c] = run; g_cstart[c] = run; run += tot[c]; }
    }
    __syncthreads();

#pragma unroll
    for (int c = 0; c < NC; c++) lc[c] = 0;
    for (int i = 0; i < 32; i++) {
        int gi = base + i;
        int c  = sl[gi];
        int pos = cst[c] + cnt[c][tid] + lc[c]++;
        g_order[pos] = gi;
        g_scls[pos]  = c;
        g_sx2[pos]   = g_x2[gi];
    }
}

// ---------------------------------------------------------------------------
// Kernel 3: symmetric-tile Gram, k-chunk software pipeline (4 x 32, double-
// buffered SMEM chunks, register-staged prefetch). Off-diagonal tiles feed
// both row-side and col-side stats; sorted order => block spans <= 2 classes.
// ---------------------------------------------------------------------------
__global__ __launch_bounds__(256, 1)
void bh_main(const float* __restrict__ E)
{
    extern __shared__ float sm[];
    float* As  = sm;                    // [2][KC][BT]
    float* Bsm = As + 2 * KC * BT;      // [2][KC][BT]
    float* sCA = Bsm + 2 * KC * BT;     // [16][128]
    float* sCB = sCA + 16 * 128;        // [16][128]
    float* sMp = sCB + 16 * 128;        // [16][128]
    float* sxj = sMp + 16 * 128;        // [128]
    __shared__ int sb_col, sb_row;

    const int tid = threadIdx.x;
    const int tx  = tid & 15;
    const int ty  = tid >> 4;

    // triangular decode
    int b = blockIdx.x, bi = 0;
    while (b >= NB - bi) { b -= NB - bi; ++bi; }
    const int bj = bi + b;
    const bool diag = (bi == bj);
    const int rowbase = bi * BT;
    const int jbase   = bj * BT;

    if (tid == 0) { sb_col = BT; sb_row = BT; }
    __syncthreads();
    if (tid < BT - 1) {
        if (g_scls[jbase + tid + 1]   != g_scls[jbase + tid])   atomicMin(&sb_col, tid + 1);
        if (g_scls[rowbase + tid + 1] != g_scls[rowbase + tid]) atomicMin(&sb_row, tid + 1);
    }
    if (tid < BT) sxj[tid] = g_sx2[jbase + tid];

    // per-thread source pointers for chunk staging: 4 (r,k4) slots each
    const int r_  = tid & (BT - 1);          // stage covers rows via idx scheme
    // chunk element layout: idx = tid + it*256, it 0..3 ; r = idx&127, k4 = idx>>7
    const float* aSrc[4];
    const float* bSrc[4];
#pragma unroll
    for (int it = 0; it < 4; ++it) {
        int idx = tid + it * 256;
        int r = idx & (BT - 1);
        aSrc[it] = E + (size_t)g_order[rowbase + r] * DD;
        bSrc[it] = E + (size_t)g_order[jbase + r] * DD;
    }
    (void)r_;

    // ---- load chunk 0 directly ----
#pragma unroll
    for (int it = 0; it < 4; ++it) {
        int idx = tid + it * 256;
        int r = idx & (BT - 1), k4 = idx >> 7;
        float4 va = *reinterpret_cast<const float4*>(aSrc[it] + k4 * 4);
        float4 vb = *reinterpret_cast<const float4*>(bSrc[it] + k4 * 4);
        As[(k4 * 4 + 0) * BT + r] = va.x;  As[(k4 * 4 + 1) * BT + r] = va.y;
        As[(k4 * 4 + 2) * BT + r] = va.z;  As[(k4 * 4 + 3) * BT + r] = va.w;
        Bsm[(k4 * 4 + 0) * BT + r] = vb.x; Bsm[(k4 * 4 + 1) * BT + r] = vb.y;
        Bsm[(k4 * 4 + 2) * BT + r] = vb.z; Bsm[(k4 * 4 + 3) * BT + r] = vb.w;
    }
    __syncthreads();

    unsigned long long acc[8][4];
#pragma unroll
    for (int i = 0; i < 8; ++i)
#pragma unroll
        for (int m = 0; m < 4; ++m) acc[i][m] = 0ull;

#pragma unroll
    for (int c = 0; c < NCHUNK; ++c) {
        const int p = c & 1;
        const float* Ab = As  + p * KC * BT;
        const float* Bb = Bsm + p * KC * BT;
        float* An = As  + (p ^ 1) * KC * BT;
        float* Bn = Bsm + (p ^ 1) * KC * BT;

        float4 stA[4], stB[4];
        if (c + 1 < NCHUNK) {
#pragma unroll
            for (int it = 0; it < 4; ++it) {
                int idx = tid + it * 256;
                int k4 = idx >> 7;
                stA[it] = *reinterpret_cast<const float4*>(aSrc[it] + (c + 1) * KC + k4 * 4);
                stB[it] = *reinterpret_cast<const float4*>(bSrc[it] + (c + 1) * KC + k4 * 4);
            }
        }

#pragma unroll 4
        for (int k = 0; k < KC; ++k) {
            float4 a0 = *reinterpret_cast<const float4*>(&Ab[k * BT + ty * 8]);
            float4 a1 = *reinterpret_cast<const float4*>(&Ab[k * BT + ty * 8 + 4]);
            unsigned long long bb[4];
#pragma unroll
            for (int m = 0; m < 4; ++m)
                bb[m] = *reinterpret_cast<const unsigned long long*>(
                    &Bb[k * BT + tx * 2 + 32 * m]);
            unsigned long long av[8];
            PACK2(av[0], a0.x); PACK2(av[1], a0.y); PACK2(av[2], a0.z); PACK2(av[3], a0.w);
            PACK2(av[4], a1.x); PACK2(av[5], a1.y); PACK2(av[6], a1.z); PACK2(av[7], a1.w);
#pragma unroll
            for (int i = 0; i < 8; ++i)
#pragma unroll
                for (int m = 0; m < 4; ++m)
                    FFMA2(acc[i][m], av[i], bb[m]);
        }

        if (c + 1 < NCHUNK) {
#pragma unroll
            for (int it = 0; it < 4; ++it) {
                int idx = tid + it * 256;
                int r = idx & (BT - 1), k4 = idx >> 7;
                An[(k4 * 4 + 0) * BT + r] = stA[it].x;
                An[(k4 * 4 + 1) * BT + r] = stA[it].y;
                An[(k4 * 4 + 2) * BT + r] = stA[it].z;
                An[(k4 * 4 + 3) * BT + r] = stA[it].w;
                Bn[(k4 * 4 + 0) * BT + r] = stB[it].x;
                Bn[(k4 * 4 + 1) * BT + r] = stB[it].y;
                Bn[(k4 * 4 + 2) * BT + r] = stB[it].z;
                Bn[(k4 * 4 + 3) * BT + r] = stB[it].w;
            }
            __syncthreads();
        }
    }

    // ---- epilogue ----
    const int scol = sb_col, srow = sb_row;
    const int cAc = g_scls[jbase],   cBc = g_scls[jbase + BT - 1];
    const int cAr = g_scls[rowbase], cBr = g_scls[rowbase + BT - 1];

    float ax[8];
    int   rcls[8];
#pragma unroll
    for (int i = 0; i < 8; ++i) {
        ax[i]   = g_sx2[rowbase + ty * 8 + i];
        rcls[i] = (ty * 8 + i < srow) ? cAr : cBr;
    }
    float accA[8], accB[8], mpv[8];
#pragma unroll
    for (int i = 0; i < 8; ++i) { accA[i] = 0.f; accB[i] = 0.f; mpv[i] = 0.f; }

#pragma unroll
    for (int m = 0; m < 4; ++m) {
#pragma unroll
        for (int p = 0; p < 2; ++p) {
            const int  col  = tx * 2 + 32 * m + p;
            const bool isA  = col < scol;
            const int  ccol = isA ? cAc : cBc;
            const float xj  = sxj[col];
            float sA = 0.f, sB = 0.f, mpc = 0.f;
#pragma unroll
            for (int i = 0; i < 8; ++i) {
                unsigned long long v = acc[i][m];
                float dot = __uint_as_float(
                    p ? (unsigned)(v >> 32) : (unsigned)(v & 0xffffffffu));
                float d = fmaxf(fmaf(-2.0f, dot, ax[i] + xj), 0.0f);
                if (isA) accA[i] += d; else accB[i] += d;
                if (rcls[i] == ccol) { mpv[i] = fmaxf(mpv[i], d); mpc = fmaxf(mpc, d); }
                if (ty * 8 + i < srow) sA += d; else sB += d;
            }
            if (!diag) {
                sCA[ty * 128 + col] = sA;
                sCB[ty * 128 + col] = sB;
                sMp[ty * 128 + col] = mpc;
            }
        }
    }

    // row-side reduce across tx and publish
#pragma unroll
    for (int off = 8; off >= 1; off >>= 1) {
#pragma unroll
        for (int i = 0; i < 8; ++i) {
            accA[i] += __shfl_down_sync(0xffffffffu, accA[i], off, 16);
            accB[i] += __shfl_down_sync(0xffffffffu, accB[i], off, 16);
            mpv[i]   = fmaxf(mpv[i], __shfl_down_sync(0xffffffffu, mpv[i], off, 16));
        }
    }
    if (tx == 0) {
#pragma unroll
        for (int i = 0; i < 8; ++i) {
            const int rp = rowbase + ty * 8 + i;
            atomicAdd(&g_S[rp][cAc], accA[i]);
            if (scol < BT) atomicAdd(&g_S[rp][cBc], accB[i]);
            atomicMax(&g_mp[rp], __float_as_uint(mpv[i]));
        }
    }

    // col-side reduce and publish (off-diagonal only)
    if (!diag) {
        __syncthreads();
        if (tid < BT) {
            const int col = tid;
            float sA = 0.f, sB = 0.f;
#pragma unroll
            for (int t2 = 0; t2 < 16; ++t2) {
                sA += sCA[t2 * 128 + col];
                sB += sCB[t2 * 128 + col];
            }
            const int cp = jbase + col;
            atomicAdd(&g_S[cp][cAr], sA);
            if (srow < BT) atomicAdd(&g_S[cp][cBr], sB);
        } else {
            const int col = tid - BT;
            float mpc = 0.f;
#pragma unroll
            for (int t2 = 0; t2 < 16; ++t2)
                mpc = fmaxf(mpc, sMp[t2 * 128 + col]);
            atomicMax(&g_mp[jbase + col], __float_as_uint(mpc));
        }
    }
}

// ---------------------------------------------------------------------------
// Kernel 4: finalize — warp per sorted anchor: argmin, class walk, exact d_neg
// ---------------------------------------------------------------------------
__global__ void bh_final(const float* __restrict__ E, float* __restrict__ out)
{
    const int p    = (blockIdx.x * blockDim.x + threadIdx.x) >> 5;
    const int lane = threadIdx.x & 31;

    float T = 0.f, S[NC];
#pragma unroll
    for (int c = 0; c < NC; c++) { S[c] = g_S[p][c]; T += S[c]; }

    float best = 3.4e38f;
    int   ks   = 0;
#pragma unroll
    for (int c = 0; c < NC; c++) {
        float nd = T - S[c];
        if (nd < best) { best = nd; ks = c; }
    }

    const int la = g_scls[p];
    int rem = ks, js = 0;
#pragma unroll
    for (int c = 0; c < NC; c++) {
        if (c == la) continue;
        int cn = g_count[c];
        if (rem < cn) { js = g_order[g_cstart[c] + rem]; rem = 0x7fffffff; }
        else rem -= cn;
    }

    const int gi = g_order[p];
    float4 a = *reinterpret_cast<const float4*>(E + (size_t)gi * DD + lane * 4);
    float4 bv = *reinterpret_cast<const float4*>(E + (size_t)js * DD + lane * 4);
    float dot = a.x * bv.x + a.y * bv.y + a.z * bv.z + a.w * bv.w;
#pragma unroll
    for (int off = 16; off >= 1; off >>= 1)
        dot += __shfl_xor_sync(0xffffffffu, dot, off);

    float loss = 0.f;
    if (lane == 0) {
        float dn = fmaxf(g_x2[gi] + g_x2[js] - 2.0f * dot, 0.0f);
        loss = fmaxf(__uint_as_float(g_mp[p]) - dn + 1.0f, 0.0f);
    }

    __shared__ float wsum[8];
    if (lane == 0) wsum[threadIdx.x >> 5] = loss;
    __syncthreads();
    if (threadIdx.x == 0) {
        float s = 0.f;
#pragma unroll
        for (int w = 0; w < 8; w++) s += wsum[w];
        atomicAdd(out, s * (1.0f / NN));
    }
}

// ---------------------------------------------------------------------------
extern "C" void kernel_launch(void* const* d_in, const int* in_sizes, int n_in,
                              void* d_out, int out_size)
{
    const float* E      = (const float*)d_in[0];
    const int*   labels = (const int*)d_in[1];
    float*       out    = (float*)d_out;

    const int smem = (4 * KC * BT + 3 * 16 * 128 + 128) * 4;
    cudaFuncSetAttribute(bh_main, cudaFuncAttributeMaxDynamicSharedMemorySize, smem);

    bh_prep<<<NN * 32 / 256, 256>>>(E, out);
    bh_table<<<1, 256>>>(labels);
    bh_main<<<NTILES, 256, smem>>>(E);
    bh_final<<<NN * 32 / 256, 256>>>(E, out);
}

// round 8
// speedup vs baseline: 1.0671x; 1.0671x over previous
#include <cuda_runtime.h>
#include <cstdint>

#define NN 8192
#define DD 128
#define NC 10
#define BT 128                 // tile edge
#define NB (NN / BT)           // 64 blocks per axis
#define NTILES (NB * (NB + 1) / 2)   // 2080

// ---- device globals ----
__device__ float    g_x2[NN];
__device__ float    g_S[NN][NC];      // indexed by SORTED position
__device__ unsigned g_mp[NN];         // indexed by SORTED position
__device__ int      g_order[NN];
__device__ int      g_scls[NN];
__device__ float    g_sx2[NN];
__device__ int      g_cstart[NC];
__device__ int      g_count[NC];

#define FFMA2(acc, a, b) \
    asm("fma.rn.f32x2 %0, %1, %2, %0;" : "+l"(acc) : "l"(a), "l"(b))
#define PACK2(dst, f) \
    asm("mov.b64 %0, {%1, %1};" : "=l"(dst) : "r"(__float_as_uint(f)))

// ---------------------------------------------------------------------------
// Kernel 1: warp-per-row norms + zero g_S, g_mp, out
// ---------------------------------------------------------------------------
__global__ void bh_prep(const float* __restrict__ E, float* __restrict__ out)
{
    const int gw   = (blockIdx.x * blockDim.x + threadIdx.x) >> 5;
    const int lane = threadIdx.x & 31;
    if (blockIdx.x == 0 && threadIdx.x == 0) out[0] = 0.0f;
    if (gw < NN) {
        float4 v = *reinterpret_cast<const float4*>(E + (size_t)gw * DD + lane * 4);
        float s = v.x * v.x + v.y * v.y + v.z * v.z + v.w * v.w;
#pragma unroll
        for (int off = 16; off >= 1; off >>= 1)
            s += __shfl_xor_sync(0xffffffffu, s, off);
        if (lane == 0) { g_x2[gw] = s; g_mp[gw] = 0u; }
        if (lane < NC) g_S[gw][lane] = 0.f;
    }
}

// ---------------------------------------------------------------------------
// Kernel 2: counts, class starts, stable (class,index) sort -> order/cls/x2
// ---------------------------------------------------------------------------
__global__ void bh_table(const int* __restrict__ labels)
{
    __shared__ int sl[NN];
    __shared__ int cnt[NC][256];
    __shared__ int tot[NC], cst[NC];

    const int tid = threadIdx.x;
    for (int i = tid; i < NN; i += 256) sl[i] = labels[i];
    __syncthreads();

    const int base = tid * 32;
    int lc[NC];
#pragma unroll
    for (int c = 0; c < NC; c++) lc[c] = 0;
    for (int i = 0; i < 32; i++) {
        int lbl = sl[base + i];
#pragma unroll
        for (int c = 0; c < NC; c++) lc[c] += (lbl == c);
    }
#pragma unroll
    for (int c = 0; c < NC; c++) cnt[c][tid] = lc[c];
    __syncthreads();

    if (tid < NC) {
        int run = 0;
        for (int t = 0; t < 256; t++) { int tmp = cnt[tid][t]; cnt[tid][t] = run; run += tmp; }
        tot[tid] = run;
        g_count[tid] = run;
    }
    __syncthreads();
    if (tid == 0) {
        int run = 0;
        for (int c = 0; c < NC; c++) { cst[c] = run; g_cstart[c] = run; run += tot[c]; }
    }
    __syncthreads();

#pragma unroll
    for (int c = 0; c < NC; c++) lc[c] = 0;
    for (int i = 0; i < 32; i++) {
        int gi = base + i;
        int c  = sl[gi];
        int pos = cst[c] + cnt[c][tid] + lc[c]++;
        g_order[pos] = gi;
        g_scls[pos]  = c;
        g_sx2[pos]   = g_x2[gi];
    }
}

// ---------------------------------------------------------------------------
// Kernel 3: symmetric-tile Gram (round-6 structure: monolithic tile load,
// single sync). Off-diagonal tiles feed both row-side and col-side stats;
// sorted order => each 128-block spans <= 2 classes.
// ---------------------------------------------------------------------------
__global__ __launch_bounds__(256, 1)
void bh_main(const float* __restrict__ E)
{
    extern __shared__ float sm[];
    float* As  = sm;                    // [DD][BT]
    float* Bsm = As + DD * BT;          // [DD][BT]
    float* sCA = Bsm + DD * BT;         // [16][128] col-side sums, row-class A
    float* sCB = sCA + 16 * 128;        // [16][128] col-side sums, row-class B
    float* sMp = sCB + 16 * 128;        // [16][128] col-side same-class max
    float* sxj = sMp + 16 * 128;        // [128]
    __shared__ int sb_col, sb_row;

    const int tid = threadIdx.x;
    const int tx  = tid & 15;
    const int ty  = tid >> 4;

    // closed-form triangular decode: bi = first block-row of this tile
    const float bf = (float)blockIdx.x;
    int bi = (int)(63.5f - sqrtf(fmaxf(63.5f * 63.5f - 2.0f * bf + 0.25f, 0.0f)));
    while ((bi + 1) * NB - ((bi + 1) * bi) / 2 <= blockIdx.x) ++bi;   // fix rounding
    while (bi * NB - (bi * (bi - 1)) / 2 > blockIdx.x) --bi;
    const int bj = bi + (blockIdx.x - (bi * NB - (bi * (bi - 1)) / 2));
    const bool diag = (bi == bj);
    const int rowbase = bi * BT;
    const int jbase   = bj * BT;

    if (tid == 0) { sb_col = BT; sb_row = BT; }
    __syncthreads();
    if (tid < BT - 1) {
        if (g_scls[jbase + tid + 1]   != g_scls[jbase + tid])   atomicMin(&sb_col, tid + 1);
        if (g_scls[rowbase + tid + 1] != g_scls[rowbase + tid]) atomicMin(&sb_row, tid + 1);
    }

    // ---- load A (and B if off-diagonal), k-major, gathered by sorted order
#pragma unroll
    for (int it = 0; it < 16; ++it) {
        int idx = tid + it * 256;
        int r   = idx & (BT - 1);
        int k4  = idx >> 7;
        float4 v = *reinterpret_cast<const float4*>(
            E + (size_t)g_order[rowbase + r] * DD + k4 * 4);
        As[(k4 * 4 + 0) * BT + r] = v.x;
        As[(k4 * 4 + 1) * BT + r] = v.y;
        As[(k4 * 4 + 2) * BT + r] = v.z;
        As[(k4 * 4 + 3) * BT + r] = v.w;
    }
    if (!diag) {
#pragma unroll
        for (int it = 0; it < 16; ++it) {
            int idx = tid + it * 256;
            int r   = idx & (BT - 1);
            int k4  = idx >> 7;
            float4 v = *reinterpret_cast<const float4*>(
                E + (size_t)g_order[jbase + r] * DD + k4 * 4);
            Bsm[(k4 * 4 + 0) * BT + r] = v.x;
            Bsm[(k4 * 4 + 1) * BT + r] = v.y;
            Bsm[(k4 * 4 + 2) * BT + r] = v.z;
            Bsm[(k4 * 4 + 3) * BT + r] = v.w;
        }
    }
    if (tid < BT) sxj[tid] = g_sx2[jbase + tid];
    __syncthreads();

    const float* Bs = diag ? As : Bsm;
    const int scol = sb_col, srow = sb_row;
    const int cAc = g_scls[jbase],   cBc = g_scls[jbase + BT - 1];
    const int cAr = g_scls[rowbase], cBr = g_scls[rowbase + BT - 1];

    // ---- 128x128x128 gram, 8x8 micro-tile, j-packed f32x2 ----
    unsigned long long acc[8][4];
#pragma unroll
    for (int i = 0; i < 8; ++i)
#pragma unroll
        for (int m = 0; m < 4; ++m) acc[i][m] = 0ull;

#pragma unroll 4
    for (int k = 0; k < DD; ++k) {
        float4 a0 = *reinterpret_cast<const float4*>(&As[k * BT + ty * 8]);
        float4 a1 = *reinterpret_cast<const float4*>(&As[k * BT + ty * 8 + 4]);
        unsigned long long bb[4];
#pragma unroll
        for (int m = 0; m < 4; ++m)
            bb[m] = *reinterpret_cast<const unsigned long long*>(
                &Bs[k * BT + tx * 2 + 32 * m]);
        unsigned long long av[8];
        PACK2(av[0], a0.x); PACK2(av[1], a0.y); PACK2(av[2], a0.z); PACK2(av[3], a0.w);
        PACK2(av[4], a1.x); PACK2(av[5], a1.y); PACK2(av[6], a1.z); PACK2(av[7], a1.w);
#pragma unroll
        for (int i = 0; i < 8; ++i)
#pragma unroll
            for (int m = 0; m < 4; ++m)
                FFMA2(acc[i][m], av[i], bb[m]);
    }

    // ---- epilogue ----
    float ax[8];
    int   rcls[8];
#pragma unroll
    for (int i = 0; i < 8; ++i) {
        ax[i]   = g_sx2[rowbase + ty * 8 + i];
        rcls[i] = (ty * 8 + i < srow) ? cAr : cBr;
    }
    float accA[8], accB[8], mpv[8];
#pragma unroll
    for (int i = 0; i < 8; ++i) { accA[i] = 0.f; accB[i] = 0.f; mpv[i] = 0.f; }

#pragma unroll
    for (int m = 0; m < 4; ++m) {
#pragma unroll
        for (int p = 0; p < 2; ++p) {
            const int  col  = tx * 2 + 32 * m + p;
            const bool isA  = col < scol;
            const int  ccol = isA ? cAc : cBc;
            const float xj  = sxj[col];
            float sA = 0.f, sB = 0.f, mpc = 0.f;
#pragma unroll
            for (int i = 0; i < 8; ++i) {
                unsigned long long v = acc[i][m];
                float dot = __uint_as_float(
                    p ? (unsigned)(v >> 32) : (unsigned)(v & 0xffffffffu));
                float d = fmaxf(fmaf(-2.0f, dot, ax[i] + xj), 0.0f);
                if (isA) accA[i] += d; else accB[i] += d;          // row-side sums
                if (rcls[i] == ccol) { mpv[i] = fmaxf(mpv[i], d); mpc = fmaxf(mpc, d); }
                if (ty * 8 + i < srow) sA += d; else sB += d;      // col-side sums
            }
            if (!diag) {
                sCA[ty * 128 + col] = sA;
                sCB[ty * 128 + col] = sB;
                sMp[ty * 128 + col] = mpc;
            }
        }
    }

    // row-side reduce across tx (width-16 shfl) and publish
#pragma unroll
    for (int off = 8; off >= 1; off >>= 1) {
#pragma unroll
        for (int i = 0; i < 8; ++i) {
            accA[i] += __shfl_down_sync(0xffffffffu, accA[i], off, 16);
            accB[i] += __shfl_down_sync(0xffffffffu, accB[i], off, 16);
            mpv[i]   = fmaxf(mpv[i], __shfl_down_sync(0xffffffffu, mpv[i], off, 16));
        }
    }
    if (tx == 0) {
#pragma unroll
        for (int i = 0; i < 8; ++i) {
            const int rp = rowbase + ty * 8 + i;
            atomicAdd(&g_S[rp][cAc], accA[i]);
            if (scol < BT) atomicAdd(&g_S[rp][cBc], accB[i]);
            atomicMax(&g_mp[rp], __float_as_uint(mpv[i]));
        }
    }

    // col-side reduce and publish (off-diagonal only)
    if (!diag) {
        __syncthreads();
        if (tid < BT) {
            const int col = tid;
            float sA = 0.f, sB = 0.f;
#pragma unroll
            for (int t2 = 0; t2 < 16; ++t2) {
                sA += sCA[t2 * 128 + col];
                sB += sCB[t2 * 128 + col];
            }
            const int cp = jbase + col;
            atomicAdd(&g_S[cp][cAr], sA);
            if (srow < BT) atomicAdd(&g_S[cp][cBr], sB);
        } else {
            const int col = tid - BT;
            float mpc = 0.f;
#pragma unroll
            for (int t2 = 0; t2 < 16; ++t2)
                mpc = fmaxf(mpc, sMp[t2 * 128 + col]);
            atomicMax(&g_mp[jbase + col], __float_as_uint(mpc));
        }
    }
}

// ---------------------------------------------------------------------------
// Kernel 4: finalize — warp per sorted anchor: argmin, class walk, exact d_neg
// ---------------------------------------------------------------------------
__global__ void bh_final(const float* __restrict__ E, float* __restrict__ out)
{
    const int p    = (blockIdx.x * blockDim.x + threadIdx.x) >> 5;
    const int lane = threadIdx.x & 31;

    float T = 0.f, S[NC];
#pragma unroll
    for (int c = 0; c < NC; c++) { S[c] = g_S[p][c]; T += S[c]; }

    float best = 3.4e38f;
    int   ks   = 0;
#pragma unroll
    for (int c = 0; c < NC; c++) {
        float nd = T - S[c];
        if (nd < best) { best = nd; ks = c; }
    }

    const int la = g_scls[p];
    int rem = ks, js = 0;
#pragma unroll
    for (int c = 0; c < NC; c++) {
        if (c == la) continue;
        int cn = g_count[c];
        if (rem < cn) { js = g_order[g_cstart[c] + rem]; rem = 0x7fffffff; }
        else rem -= cn;
    }

    const int gi = g_order[p];
    float4 a  = *reinterpret_cast<const float4*>(E + (size_t)gi * DD + lane * 4);
    float4 bv = *reinterpret_cast<const float4*>(E + (size_t)js * DD + lane * 4);
    float dot = a.x * bv.x + a.y * bv.y + a.z * bv.z + a.w * bv.w;
#pragma unroll
    for (int off = 16; off >= 1; off >>= 1)
        dot += __shfl_xor_sync(0xffffffffu, dot, off);

    float loss = 0.f;
    if (lane == 0) {
        float dn = fmaxf(g_x2[gi] + g_x2[js] - 2.0f * dot, 0.0f);
        loss = fmaxf(__uint_as_float(g_mp[p]) - dn + 1.0f, 0.0f);
    }

    __shared__ float wsum[8];
    if (lane == 0) wsum[threadIdx.x >> 5] = loss;
    __syncthreads();
    if (threadIdx.x == 0) {
        float s = 0.f;
#pragma unroll
        for (int w = 0; w < 8; w++) s += wsum[w];
        atomicAdd(out, s * (1.0f / NN));
    }
}

// ---------------------------------------------------------------------------
extern "C" void kernel_launch(void* const* d_in, const int* in_sizes, int n_in,
                              void* d_out, int out_size)
{
    const float* E      = (const float*)d_in[0];
    const int*   labels = (const int*)d_in[1];
    float*       out    = (float*)d_out;

    const int smem = (2 * DD * BT + 3 * 16 * 128 + 128) * 4;
    cudaFuncSetAttribute(bh_main, cudaFuncAttributeMaxDynamicSharedMemorySize, smem);

    bh_prep<<<NN * 32 / 256, 256>>>(E, out);
    bh_table<<<1, 256>>>(labels);
    bh_main<<<NTILES, 256, smem>>>(E);
    bh_final<<<NN * 32 / 256, 256>>>(E, out);
}

// round 9
// speedup vs baseline: 1.5515x; 1.4540x over previous
#include <cuda_runtime.h>
#include <cuda_fp16.h>
#include <cstdint>

#define NN 8192
#define DD 128
#define NC 10
#define BT 128
#define NB (NN / BT)
#define NTILES (NB * (NB + 1) / 2)   // 2080
#define RS 132                        // smem tile row stride (half2 units)

typedef unsigned long long ull;

// ---- device globals ----
__device__ float    g_x2[NN];
__device__ float    g_S[NN][NC];      // sorted-position indexed
__device__ ull      g_mpk[NN];        // (f32bits(d_pos)<<32)|sorted_col_idx
__device__ int      g_order[NN];
__device__ int      g_scls[NN];
__device__ float    g_sx2[NN];
__device__ int      g_cstart[NC];
__device__ int      g_count[NC];
__device__ __half2  g_EhT[64][NN];    // kp-major, sorted columns

__device__ __forceinline__ __half2 u2h(unsigned u) {
    __half2 h; *(unsigned*)&h = u; return h;
}

// ---------------------------------------------------------------------------
// Kernel 1: warp-per-row norms + zero g_S, g_mpk, out
// ---------------------------------------------------------------------------
__global__ void bh_prep(const float* __restrict__ E, float* __restrict__ out)
{
    const int gw   = (blockIdx.x * blockDim.x + threadIdx.x) >> 5;
    const int lane = threadIdx.x & 31;
    if (blockIdx.x == 0 && threadIdx.x == 0) out[0] = 0.0f;
    if (gw < NN) {
        float4 v = *reinterpret_cast<const float4*>(E + (size_t)gw * DD + lane * 4);
        float s = v.x * v.x + v.y * v.y + v.z * v.z + v.w * v.w;
#pragma unroll
        for (int off = 16; off >= 1; off >>= 1)
            s += __shfl_xor_sync(0xffffffffu, s, off);
        if (lane == 0) { g_x2[gw] = s; g_mpk[gw] = 0ull; }
        if (lane < NC) g_S[gw][lane] = 0.f;
    }
}

// ---------------------------------------------------------------------------
// Kernel 2: counts, class starts, stable (class,index) sort
// ---------------------------------------------------------------------------
__global__ void bh_table(const int* __restrict__ labels)
{
    __shared__ int sl[NN];
    __shared__ int cnt[NC][256];
    __shared__ int tot[NC], cst[NC];

    const int tid = threadIdx.x;
    for (int i = tid; i < NN; i += 256) sl[i] = labels[i];
    __syncthreads();

    const int base = tid * 32;
    int lc[NC];
#pragma unroll
    for (int c = 0; c < NC; c++) lc[c] = 0;
    for (int i = 0; i < 32; i++) {
        int lbl = sl[base + i];
#pragma unroll
        for (int c = 0; c < NC; c++) lc[c] += (lbl == c);
    }
#pragma unroll
    for (int c = 0; c < NC; c++) cnt[c][tid] = lc[c];
    __syncthreads();

    if (tid < NC) {
        int run = 0;
        for (int t = 0; t < 256; t++) { int tmp = cnt[tid][t]; cnt[tid][t] = run; run += tmp; }
        tot[tid] = run;
        g_count[tid] = run;
    }
    __syncthreads();
    if (tid == 0) {
        int run = 0;
        for (int c = 0; c < NC; c++) { cst[c] = run; g_cstart[c] = run; run += tot[c]; }
    }
    __syncthreads();

#pragma unroll
    for (int c = 0; c < NC; c++) lc[c] = 0;
    for (int i = 0; i < 32; i++) {
        int gi = base + i;
        int c  = sl[gi];
        int pos = cst[c] + cnt[c][tid] + lc[c]++;
        g_order[pos] = gi;
        g_scls[pos]  = c;
        g_sx2[pos]   = g_x2[gi];
    }
}

// ---------------------------------------------------------------------------
// Kernel 2b: pack sorted rows to fp16, kp-major global layout
// ---------------------------------------------------------------------------
__global__ void bh_pack(const float* __restrict__ E)
{
    const int p    = (blockIdx.x * blockDim.x + threadIdx.x) >> 5;
    const int lane = threadIdx.x & 31;
    const int gi = g_order[p];
    float4 v = *reinterpret_cast<const float4*>(E + (size_t)gi * DD + lane * 4);
    g_EhT[lane * 2][p]     = __floats2half2_rn(v.x, v.y);
    g_EhT[lane * 2 + 1][p] = __floats2half2_rn(v.z, v.w);
}

// ---------------------------------------------------------------------------
// Kernel 3: symmetric-tile Gram in fp16 (HFMA2, k-packed), 2 CTAs/SM.
// ---------------------------------------------------------------------------
__global__ __launch_bounds__(256, 2)
void bh_main()
{
    extern __shared__ char smraw[];
    __half2* Ah = (__half2*)smraw;               // [64][RS]
    __half2* Bh = Ah + 64 * RS;                  // [64][RS]
    float* sCA  = (float*)(Bh + 64 * RS);        // [16][128]
    float* sCB  = sCA + 16 * 128;                // [16][128]
    ull*   sMpK = (ull*)(sCB + 16 * 128);        // [16][128]
    float* sxj  = (float*)(sMpK + 16 * 128);     // [128]
    __shared__ int sb_col, sb_row;

    const int tid = threadIdx.x;
    const int tx  = tid & 15;
    const int ty  = tid >> 4;

    // triangular decode
    const float bf = (float)blockIdx.x;
    int bi = (int)(63.5f - sqrtf(fmaxf(63.5f * 63.5f - 2.0f * bf + 0.25f, 0.0f)));
    while ((bi + 1) * NB - ((bi + 1) * bi) / 2 <= (int)blockIdx.x) ++bi;
    while (bi * NB - (bi * (bi - 1)) / 2 > (int)blockIdx.x) --bi;
    const int bj = bi + ((int)blockIdx.x - (bi * NB - (bi * (bi - 1)) / 2));
    const bool diag = (bi == bj);
    const int rowbase = bi * BT;
    const int jbase   = bj * BT;

    if (tid == 0) { sb_col = BT; sb_row = BT; }
    __syncthreads();
    if (tid < BT - 1) {
        if (g_scls[jbase + tid + 1]   != g_scls[jbase + tid])   atomicMin(&sb_col, tid + 1);
        if (g_scls[rowbase + tid + 1] != g_scls[rowbase + tid]) atomicMin(&sb_row, tid + 1);
    }

    // ---- tile loads: coalesced LDG.128 from kp-major global, STS.128 ----
#pragma unroll
    for (int it = 0; it < 8; ++it) {
        int idx = tid + it * 256;        // 0..2047
        int kp  = idx >> 5;              // 0..63
        int u   = idx & 31;
        uint4 v = *reinterpret_cast<const uint4*>(&g_EhT[kp][rowbase + u * 4]);
        *reinterpret_cast<uint4*>(&Ah[kp * RS + u * 4]) = v;
    }
    if (!diag) {
#pragma unroll
        for (int it = 0; it < 8; ++it) {
            int idx = tid + it * 256;
            int kp  = idx >> 5;
            int u   = idx & 31;
            uint4 v = *reinterpret_cast<const uint4*>(&g_EhT[kp][jbase + u * 4]);
            *reinterpret_cast<uint4*>(&Bh[kp * RS + u * 4]) = v;
        }
    }
    if (tid < BT) sxj[tid] = g_sx2[jbase + tid];
    __syncthreads();

    const __half2* Bs = diag ? Ah : Bh;

    // ---- 128x128x128 gram: 8x8 micro-tile, HFMA2 k-pairs ----
    __half2 acc[8][8];
#pragma unroll
    for (int i = 0; i < 8; ++i)
#pragma unroll
        for (int j = 0; j < 8; ++j) acc[i][j] = u2h(0u);

#pragma unroll 2
    for (int kp = 0; kp < 64; ++kp) {
        uint4 a0 = *reinterpret_cast<const uint4*>(&Ah[kp * RS + ty * 8]);
        uint4 a1 = *reinterpret_cast<const uint4*>(&Ah[kp * RS + ty * 8 + 4]);
        uint4 b0 = *reinterpret_cast<const uint4*>(&Bs[kp * RS + tx * 8]);
        uint4 b1 = *reinterpret_cast<const uint4*>(&Bs[kp * RS + tx * 8 + 4]);
        __half2 av[8] = {u2h(a0.x), u2h(a0.y), u2h(a0.z), u2h(a0.w),
                         u2h(a1.x), u2h(a1.y), u2h(a1.z), u2h(a1.w)};
        __half2 bv[8] = {u2h(b0.x), u2h(b0.y), u2h(b0.z), u2h(b0.w),
                         u2h(b1.x), u2h(b1.y), u2h(b1.z), u2h(b1.w)};
#pragma unroll
        for (int i = 0; i < 8; ++i)
#pragma unroll
            for (int j = 0; j < 8; ++j)
                acc[i][j] = __hfma2(av[i], bv[j], acc[i][j]);
    }

    // ---- epilogue ----
    const int scol = sb_col, srow = sb_row;
    const int cAc = g_scls[jbase],   cBc = g_scls[jbase + BT - 1];
    const int cAr = g_scls[rowbase], cBr = g_scls[rowbase + BT - 1];

    float ax[8];
    int   rcls[8];
#pragma unroll
    for (int i = 0; i < 8; ++i) {
        ax[i]   = g_sx2[rowbase + ty * 8 + i];
        rcls[i] = (ty * 8 + i < srow) ? cAr : cBr;
    }
    float accA[8], accB[8], mv[8];
    int   mj[8];
#pragma unroll
    for (int i = 0; i < 8; ++i) { accA[i] = 0.f; accB[i] = 0.f; mv[i] = -1.f; mj[i] = 0; }

#pragma unroll
    for (int jj = 0; jj < 8; ++jj) {
        const int  col  = tx * 8 + jj;
        const bool isA  = col < scol;
        const int  ccol = isA ? cAc : cBc;
        const float xj  = sxj[col];
        float sA = 0.f, sB = 0.f, cv = -1.f;
        int   ci = 0;
#pragma unroll
        for (int ii = 0; ii < 8; ++ii) {
            float2 f = __half22float2(acc[ii][jj]);
            float d = fmaxf(fmaf(-2.0f, f.x + f.y, ax[ii] + xj), 0.0f);
            if (isA) accA[ii] += d; else accB[ii] += d;
            if (rcls[ii] == ccol) {
                if (d > mv[ii]) { mv[ii] = d; mj[ii] = col; }
                if (d > cv)     { cv = d; ci = ii; }
            }
            if (ty * 8 + ii < srow) sA += d; else sB += d;
        }
        if (!diag) {
            sCA[ty * 128 + col] = sA;
            sCB[ty * 128 + col] = sB;
            sMpK[ty * 128 + col] = (cv >= 0.f)
                ? ((((ull)__float_as_uint(cv)) << 32) | (unsigned)(rowbase + ty * 8 + ci))
                : 0ull;
        }
    }

    // row-side reduce across tx (width-16) and publish
#pragma unroll
    for (int off = 8; off >= 1; off >>= 1) {
#pragma unroll
        for (int i = 0; i < 8; ++i) {
            accA[i] += __shfl_down_sync(0xffffffffu, accA[i], off, 16);
            accB[i] += __shfl_down_sync(0xffffffffu, accB[i], off, 16);
            float ov = __shfl_down_sync(0xffffffffu, mv[i], off, 16);
            int   oj = __shfl_down_sync(0xffffffffu, mj[i], off, 16);
            if (ov > mv[i]) { mv[i] = ov; mj[i] = oj; }
        }
    }
    if (tx == 0) {
#pragma unroll
        for (int i = 0; i < 8; ++i) {
            const int rp = rowbase + ty * 8 + i;
            atomicAdd(&g_S[rp][cAc], accA[i]);
            if (scol < BT) atomicAdd(&g_S[rp][cBc], accB[i]);
            if (mv[i] >= 0.f)
                atomicMax(&g_mpk[rp],
                          (((ull)__float_as_uint(mv[i])) << 32) | (unsigned)(jbase + mj[i]));
        }
    }

    // col-side reduce and publish (off-diagonal only)
    if (!diag) {
        __syncthreads();
        if (tid < BT) {
            const int col = tid;
            float sA = 0.f, sB = 0.f;
#pragma unroll
            for (int t2 = 0; t2 < 16; ++t2) {
                sA += sCA[t2 * 128 + col];
                sB += sCB[t2 * 128 + col];
            }
            const int cp = jbase + col;
            atomicAdd(&g_S[cp][cAr], sA);
            if (srow < BT) atomicAdd(&g_S[cp][cBr], sB);
        } else {
            const int col = tid - BT;
            ull km = 0ull;
#pragma unroll
            for (int t2 = 0; t2 < 16; ++t2) {
                ull k = sMpK[t2 * 128 + col];
                if (k > km) km = k;
            }
            if (km) atomicMax(&g_mpk[jbase + col], km);
        }
    }
}

// ---------------------------------------------------------------------------
// Kernel 4: finalize — warp per sorted anchor: argmin, class walk,
// EXACT fp32 recompute of both d_pos (tracked argmax) and d_neg.
// ---------------------------------------------------------------------------
__global__ void bh_final(const float* __restrict__ E, float* __restrict__ out)
{
    const int p    = (blockIdx.x * blockDim.x + threadIdx.x) >> 5;
    const int lane = threadIdx.x & 31;

    float T = 0.f, S[NC];
#pragma unroll
    for (int c = 0; c < NC; c++) { S[c] = g_S[p][c]; T += S[c]; }

    float best = 3.4e38f;
    int   ks   = 0;
#pragma unroll
    for (int c = 0; c < NC; c++) {
        float nd = T - S[c];
        if (nd < best) { best = nd; ks = c; }
    }

    const int la = g_scls[p];
    int rem = ks, js = 0;
#pragma unroll
    for (int c = 0; c < NC; c++) {
        if (c == la) continue;
        int cn = g_count[c];
        if (rem < cn) { js = g_order[g_cstart[c] + rem]; rem = 0x7fffffff; }
        else rem -= cn;
    }

    const ull key = g_mpk[p];
    const int jpq = (int)(key & 0xffffffffu);      // sorted idx of d_pos argmax
    const int gjp = g_order[jpq];
    const int gi  = g_order[p];

    float4 a  = *reinterpret_cast<const float4*>(E + (size_t)gi  * DD + lane * 4);
    float4 bp = *reinterpret_cast<const float4*>(E + (size_t)gjp * DD + lane * 4);
    float4 bn = *reinterpret_cast<const float4*>(E + (size_t)js  * DD + lane * 4);
    float dotp = a.x * bp.x + a.y * bp.y + a.z * bp.z + a.w * bp.w;
    float dotn = a.x * bn.x + a.y * bn.y + a.z * bn.z + a.w * bn.w;
#pragma unroll
    for (int off = 16; off >= 1; off >>= 1) {
        dotp += __shfl_xor_sync(0xffffffffu, dotp, off);
        dotn += __shfl_xor_sync(0xffffffffu, dotn, off);
    }

    float loss = 0.f;
    if (lane == 0) {
        float dp = fmaxf(g_x2[gi] + g_x2[gjp] - 2.0f * dotp, 0.0f);
        float dn = fmaxf(g_x2[gi] + g_x2[js]  - 2.0f * dotn, 0.0f);
        loss = fmaxf(dp - dn + 1.0f, 0.0f);
    }

    __shared__ float wsum[8];
    if (lane == 0) wsum[threadIdx.x >> 5] = loss;
    __syncthreads();
    if (threadIdx.x == 0) {
        float s = 0.f;
#pragma unroll
        for (int w = 0; w < 8; w++) s += wsum[w];
        atomicAdd(out, s * (1.0f / NN));
    }
}

// ---------------------------------------------------------------------------
extern "C" void kernel_launch(void* const* d_in, const int* in_sizes, int n_in,
                              void* d_out, int out_size)
{
    const float* E      = (const float*)d_in[0];
    const int*   labels = (const int*)d_in[1];
    float*       out    = (float*)d_out;

    const int smem = 64 * RS * 4 * 2          // Ah + Bh (half2)
                   + 16 * 128 * 4 * 2         // sCA + sCB
                   + 16 * 128 * 8             // sMpK
                   + 128 * 4;                 // sxj
    cudaFuncSetAttribute(bh_main, cudaFuncAttributeMaxDynamicSharedMemorySize, smem);

    bh_prep<<<NN * 32 / 256, 256>>>(E, out);
    bh_table<<<1, 256>>>(labels);
    bh_pack<<<NN * 32 / 256, 256>>>(E);
    bh_main<<<NTILES, 256, smem>>>();
    bh_final<<<NN * 32 / 256, 256>>>(E, out);
}

// round 10
// speedup vs baseline: 2.7981x; 1.8035x over previous
#include <cuda_runtime.h>
#include <cuda_fp16.h>
#include <cstdint>

#define NN 8192
#define DD 128
#define NC 10
#define BT 128
#define NB (NN / BT)
#define NTILES (NB * (NB + 1) / 2)   // 2080
#define PITCH 136                     // halves per smem tile row (272 B)
#define DPITCH 132                    // floats per d-matrix row

typedef unsigned long long ull;

// ---- device globals ----
__device__ float   g_x2[NN];
__device__ float   g_S[NN][NC];       // sorted-position indexed
__device__ ull     g_mpk[NN];         // (f32bits(d_pos)<<32)|sorted_idx
__device__ int     g_order[NN];
__device__ int     g_scls[NN];
__device__ float   g_sx2[NN];
__device__ int     g_cstart[NC];
__device__ int     g_count[NC];
__device__ __half2 g_Eh[NN][64];      // sorted rows, k-contiguous fp16

__device__ __forceinline__ uint32_t smem_u32(const void* p) {
    uint32_t a;
    asm("{ .reg .u64 t; cvta.to.shared.u64 t, %1; cvt.u32.u64 %0, t; }" : "=r"(a) : "l"(p));
    return a;
}

#define LDSM4(r0, r1, r2, r3, addr)                                          \
    asm volatile("ldmatrix.sync.aligned.m8n8.x4.shared.b16 {%0,%1,%2,%3},[%4];" \
        : "=r"(r0), "=r"(r1), "=r"(r2), "=r"(r3) : "r"(addr))

#define MMA16816(cp, a0, a1, a2, a3, b0, b1)                                 \
    asm volatile("mma.sync.aligned.m16n8k16.row.col.f32.f16.f16.f32 "        \
        "{%0,%1,%2,%3},{%4,%5,%6,%7},{%8,%9},{%0,%1,%2,%3};"                 \
        : "+f"((cp)[0]), "+f"((cp)[1]), "+f"((cp)[2]), "+f"((cp)[3])         \
        : "r"(a0), "r"(a1), "r"(a2), "r"(a3), "r"(b0), "r"(b1))

// ---------------------------------------------------------------------------
// Kernel 1: warp-per-row norms + zero g_S, g_mpk, out
// ---------------------------------------------------------------------------
__global__ void bh_prep(const float* __restrict__ E, float* __restrict__ out)
{
    const int gw   = (blockIdx.x * blockDim.x + threadIdx.x) >> 5;
    const int lane = threadIdx.x & 31;
    if (blockIdx.x == 0 && threadIdx.x == 0) out[0] = 0.0f;
    if (gw < NN) {
        float4 v = *reinterpret_cast<const float4*>(E + (size_t)gw * DD + lane * 4);
        float s = v.x * v.x + v.y * v.y + v.z * v.z + v.w * v.w;
#pragma unroll
        for (int off = 16; off >= 1; off >>= 1)
            s += __shfl_xor_sync(0xffffffffu, s, off);
        if (lane == 0) { g_x2[gw] = s; g_mpk[gw] = 0ull; }
        if (lane < NC) g_S[gw][lane] = 0.f;
    }
}

// ---------------------------------------------------------------------------
// Kernel 2: counts, class starts, stable (class,index) sort
// ---------------------------------------------------------------------------
__global__ void bh_table(const int* __restrict__ labels)
{
    __shared__ int sl[NN];
    __shared__ int cnt[NC][256];
    __shared__ int tot[NC], cst[NC];

    const int tid = threadIdx.x;
    for (int i = tid; i < NN; i += 256) sl[i] = labels[i];
    __syncthreads();

    const int base = tid * 32;
    int lc[NC];
#pragma unroll
    for (int c = 0; c < NC; c++) lc[c] = 0;
    for (int i = 0; i < 32; i++) {
        int lbl = sl[base + i];
#pragma unroll
        for (int c = 0; c < NC; c++) lc[c] += (lbl == c);
    }
#pragma unroll
    for (int c = 0; c < NC; c++) cnt[c][tid] = lc[c];
    __syncthreads();

    if (tid < NC) {
        int run = 0;
        for (int t = 0; t < 256; t++) { int tmp = cnt[tid][t]; cnt[tid][t] = run; run += tmp; }
        tot[tid] = run;
        g_count[tid] = run;
    }
    __syncthreads();
    if (tid == 0) {
        int run = 0;
        for (int c = 0; c < NC; c++) { cst[c] = run; g_cstart[c] = run; run += tot[c]; }
    }
    __syncthreads();

#pragma unroll
    for (int c = 0; c < NC; c++) lc[c] = 0;
    for (int i = 0; i < 32; i++) {
        int gi = base + i;
        int c  = sl[gi];
        int pos = cst[c] + cnt[c][tid] + lc[c]++;
        g_order[pos] = gi;
        g_scls[pos]  = c;
        g_sx2[pos]   = g_x2[gi];
    }
}

// ---------------------------------------------------------------------------
// Kernel 2b: pack sorted rows to fp16 row-major
// ---------------------------------------------------------------------------
__global__ void bh_pack(const float* __restrict__ E)
{
    const int p    = (blockIdx.x * blockDim.x + threadIdx.x) >> 5;
    const int lane = threadIdx.x & 31;
    const int gi = g_order[p];
    float4 v = *reinterpret_cast<const float4*>(E + (size_t)gi * DD + lane * 4);
    g_Eh[p][lane * 2]     = __floats2half2_rn(v.x, v.y);
    g_Eh[p][lane * 2 + 1] = __floats2half2_rn(v.z, v.w);
}

// ---------------------------------------------------------------------------
// Kernel 3: symmetric-tile Gram via HMMA (mma.sync m16n8k16 f16->f32).
// ---------------------------------------------------------------------------
__global__ __launch_bounds__(256, 2)
void bh_main()
{
    extern __shared__ char smraw[];
    const uint32_t sb = smem_u32(smraw);
    __half* Ah = (__half*)smraw;                 // [128][PITCH]
    float*  ds = (float*)smraw;                  // [128][DPITCH] (reuses A+B)
    float*  sxj = (float*)(smraw + 69632);       // [128] col norms
    float*  sxr = sxj + 128;                     // [128] row norms
    __shared__ int sb_col, sb_row;

    const int tid  = threadIdx.x;
    const int w    = tid >> 5;
    const int lane = tid & 31;

    // triangular decode
    const float bf = (float)blockIdx.x;
    int bi = (int)(63.5f - sqrtf(fmaxf(63.5f * 63.5f - 2.0f * bf + 0.25f, 0.0f)));
    while ((bi + 1) * NB - ((bi + 1) * bi) / 2 <= (int)blockIdx.x) ++bi;
    while (bi * NB - (bi * (bi - 1)) / 2 > (int)blockIdx.x) --bi;
    const int bj = bi + ((int)blockIdx.x - (bi * NB - (bi * (bi - 1)) / 2));
    const bool diag = (bi == bj);
    const int rowbase = bi * BT;
    const int jbase   = bj * BT;

    if (tid == 0) { sb_col = BT; sb_row = BT; }
    __syncthreads();
    if (tid < BT - 1) {
        if (g_scls[jbase + tid + 1]   != g_scls[jbase + tid])   atomicMin(&sb_col, tid + 1);
        if (g_scls[rowbase + tid + 1] != g_scls[rowbase + tid]) atomicMin(&sb_row, tid + 1);
    }

    // ---- tile loads: coalesced LDG.128 -> padded smem rows ----
#pragma unroll
    for (int it = 0; it < 8; ++it) {
        int idx = tid + it * 256;            // 0..2047
        int row = idx >> 4, c = idx & 15;    // 16B chunks, 16 per row
        uint4 v = *reinterpret_cast<const uint4*>(
            reinterpret_cast<const char*>(&g_Eh[rowbase + row][0]) + c * 16);
        *reinterpret_cast<uint4*>(Ah + row * PITCH + c * 8) = v;
    }
    if (!diag) {
        __half* Bh = Ah + 128 * PITCH;
#pragma unroll
        for (int it = 0; it < 8; ++it) {
            int idx = tid + it * 256;
            int row = idx >> 4, c = idx & 15;
            uint4 v = *reinterpret_cast<const uint4*>(
                reinterpret_cast<const char*>(&g_Eh[jbase + row][0]) + c * 16);
            *reinterpret_cast<uint4*>(Bh + row * PITCH + c * 8) = v;
        }
    }
    if (tid < BT) { sxj[tid] = g_sx2[jbase + tid]; sxr[tid] = g_sx2[rowbase + tid]; }
    __syncthreads();

    // ---- MMA mainloop: warp w owns rows w*16..w*16+15, all 128 cols ----
    const uint32_t aBase = sb + ((w * 16 + (lane & 15)) * PITCH + ((lane >> 4) << 3)) * 2;
    const uint32_t bTile = diag ? sb : (sb + 128 * PITCH * 2);
    const uint32_t bBase = bTile + (((lane & 7) + ((lane >> 4) << 3)) * PITCH
                                    + (((lane >> 3) & 1) << 3)) * 2;

    float cfr[16][4];
#pragma unroll
    for (int nb = 0; nb < 16; ++nb)
#pragma unroll
        for (int q = 0; q < 4; ++q) cfr[nb][q] = 0.f;

#pragma unroll
    for (int ks = 0; ks < 8; ++ks) {
        uint32_t a0, a1, a2, a3;
        LDSM4(a0, a1, a2, a3, aBase + ks * 32);
#pragma unroll
        for (int nbp = 0; nbp < 8; ++nbp) {
            uint32_t b0, b1, b2, b3;
            LDSM4(b0, b1, b2, b3, bBase + nbp * (16 * PITCH * 2) + ks * 32);
            MMA16816(cfr[2 * nbp],     a0, a1, a2, a3, b0, b1);
            MMA16816(cfr[2 * nbp + 1], a0, a1, a2, a3, b2, b3);
        }
    }
    __syncthreads();   // all smem tile reads done; safe to overwrite with d

    // ---- dump raw dot products to smem d matrix ----
    const int g = lane >> 2, t = lane & 3;
    {
        const int r0 = w * 16 + g, r1 = r0 + 8;
#pragma unroll
        for (int nb = 0; nb < 16; ++nb) {
            int colb = nb * 8 + t * 2;
            ds[r0 * DPITCH + colb]     = cfr[nb][0];
            ds[r0 * DPITCH + colb + 1] = cfr[nb][1];
            ds[r1 * DPITCH + colb]     = cfr[nb][2];
            ds[r1 * DPITCH + colb + 1] = cfr[nb][3];
        }
    }
    __syncthreads();

    const int scol = sb_col, srow = sb_row;
    const int cAc = g_scls[jbase],   cBc = g_scls[jbase + BT - 1];
    const int cAr = g_scls[rowbase], cBr = g_scls[rowbase + BT - 1];

    // ---- row pass: anchors = tile rows; thread owns half a row ----
    {
        const int row = tid >> 1, half = tid & 1;
        const float xr = sxr[row];
        const int   rc = (row < srow) ? cAr : cBr;
        float sA = 0.f, sB = 0.f, mv = -1.f;
        int   mcol = 0;
#pragma unroll 8
        for (int cc = 0; cc < 64; ++cc) {
            const int col = half * 64 + cc;
            float d = fmaxf(fmaf(-2.0f, ds[row * DPITCH + col], xr + sxj[col]), 0.0f);
            const bool isA = col < scol;
            if (isA) sA += d; else sB += d;
            if (((isA) ? cAc : cBc) == rc && d > mv) { mv = d; mcol = col; }
        }
        // combine the two halves of the row (adjacent lanes)
        sA += __shfl_down_sync(0xffffffffu, sA, 1, 2);
        sB += __shfl_down_sync(0xffffffffu, sB, 1, 2);
        float ov = __shfl_down_sync(0xffffffffu, mv, 1, 2);
        int   oc = __shfl_down_sync(0xffffffffu, mcol, 1, 2);
        if (ov > mv) { mv = ov; mcol = oc; }
        if (half == 0) {
            const int rp = rowbase + row;
            atomicAdd(&g_S[rp][cAc], sA);
            if (scol < BT) atomicAdd(&g_S[rp][cBc], sB);
            if (mv >= 0.f)
                atomicMax(&g_mpk[rp],
                          (((ull)__float_as_uint(mv)) << 32) | (unsigned)(jbase + mcol));
        }
    }

    // ---- col pass: anchors = tile cols (off-diagonal only) ----
    if (!diag) {
        const int col = tid >> 1, half = tid & 1;
        const float xc = sxj[col];
        const int   cc = (col < scol) ? cAc : cBc;
        float sA = 0.f, sB = 0.f, mv = -1.f;
        int   mrow = 0;
#pragma unroll 8
        for (int rr = 0; rr < 64; ++rr) {
            const int row = half * 64 + rr;
            float d = fmaxf(fmaf(-2.0f, ds[row * DPITCH + col], sxr[row] + xc), 0.0f);
            const bool isA = row < srow;
            if (isA) sA += d; else sB += d;
            if (((isA) ? cAr : cBr) == cc && d > mv) { mv = d; mrow = row; }
        }
        sA += __shfl_down_sync(0xffffffffu, sA, 1, 2);
        sB += __shfl_down_sync(0xffffffffu, sB, 1, 2);
        float ov = __shfl_down_sync(0xffffffffu, mv, 1, 2);
        int   or_ = __shfl_down_sync(0xffffffffu, mrow, 1, 2);
        if (ov > mv) { mv = ov; mrow = or_; }
        if (half == 0) {
            const int cp = jbase + col;
            atomicAdd(&g_S[cp][cAr], sA);
            if (srow < BT) atomicAdd(&g_S[cp][cBr], sB);
            if (mv >= 0.f)
                atomicMax(&g_mpk[cp],
                          (((ull)__float_as_uint(mv)) << 32) | (unsigned)(rowbase + mrow));
        }
    }
}

// ---------------------------------------------------------------------------
// Kernel 4: finalize — warp per sorted anchor: argmin, class walk,
// EXACT fp32 recompute of d_pos (tracked argmax) and d_neg.
// ---------------------------------------------------------------------------
__global__ void bh_final(const float* __restrict__ E, float* __restrict__ out)
{
    const int p    = (blockIdx.x * blockDim.x + threadIdx.x) >> 5;
    const int lane = threadIdx.x & 31;

    float T = 0.f, S[NC];
#pragma unroll
    for (int c = 0; c < NC; c++) { S[c] = g_S[p][c]; T += S[c]; }

    float best = 3.4e38f;
    int   ks   = 0;
#pragma unroll
    for (int c = 0; c < NC; c++) {
        float nd = T - S[c];
        if (nd < best) { best = nd; ks = c; }
    }

    const int la = g_scls[p];
    int rem = ks, js = 0;
#pragma unroll
    for (int c = 0; c < NC; c++) {
        if (c == la) continue;
        int cn = g_count[c];
        if (rem < cn) { js = g_order[g_cstart[c] + rem]; rem = 0x7fffffff; }
        else rem -= cn;
    }

    const ull key = g_mpk[p];
    const int jpq = (int)(key & 0xffffffffu);
    const int gjp = g_order[jpq];
    const int gi  = g_order[p];

    float4 a  = *reinterpret_cast<const float4*>(E + (size_t)gi  * DD + lane * 4);
    float4 bp = *reinterpret_cast<const float4*>(E + (size_t)gjp * DD + lane * 4);
    float4 bn = *reinterpret_cast<const float4*>(E + (size_t)js  * DD + lane * 4);
    float dotp = a.x * bp.x + a.y * bp.y + a.z * bp.z + a.w * bp.w;
    float dotn = a.x * bn.x + a.y * bn.y + a.z * bn.z + a.w * bn.w;
#pragma unroll
    for (int off = 16; off >= 1; off >>= 1) {
        dotp += __shfl_xor_sync(0xffffffffu, dotp, off);
        dotn += __shfl_xor_sync(0xffffffffu, dotn, off);
    }

    float loss = 0.f;
    if (lane == 0) {
        float dp = fmaxf(g_x2[gi] + g_x2[gjp] - 2.0f * dotp, 0.0f);
        float dn = fmaxf(g_x2[gi] + g_x2[js]  - 2.0f * dotn, 0.0f);
        loss = fmaxf(dp - dn + 1.0f, 0.0f);
    }

    __shared__ float wsum[8];
    if (lane == 0) wsum[threadIdx.x >> 5] = loss;
    __syncthreads();
    if (threadIdx.x == 0) {
        float s = 0.f;
#pragma unroll
        for (int w = 0; w < 8; w++) s += wsum[w];
        atomicAdd(out, s * (1.0f / NN));
    }
}

// ---------------------------------------------------------------------------
extern "C" void kernel_launch(void* const* d_in, const int* in_sizes, int n_in,
                              void* d_out, int out_size)
{
    const float* E      = (const float*)d_in[0];
    const int*   labels = (const int*)d_in[1];
    float*       out    = (float*)d_out;

    const int smem = 69632 + 2 * 128 * 4;   // A+B tiles (reused as d) + sxj + sxr
    cudaFuncSetAttribute(bh_main, cudaFuncAttributeMaxDynamicSharedMemorySize, smem);

    bh_prep<<<NN * 32 / 256, 256>>>(E, out);
    bh_table<<<1, 256>>>(labels);
    bh_pack<<<NN * 32 / 256, 256>>>(E);
    bh_main<<<NTILES, 256, smem>>>();
    bh_final<<<NN * 32 / 256, 256>>>(E, out);
}

// round 11
// speedup vs baseline: 4.0349x; 1.4420x over previous
#include <cuda_runtime.h>
#include <cuda_fp16.h>
#include <cstdint>

#define NN 8192
#define DD 128
#define NC 10
#define BT 128
#define NB (NN / BT)
#define NTILES (NB * (NB + 1) / 2)   // 2080
#define PITCH 136                     // halves per smem tile row
#define DPITCH 132                    // floats per d-matrix row

typedef unsigned long long ull;

// ---- device globals ----
__device__ float   g_x2[NN];
__device__ float   g_S[NN][NC];       // sorted-position indexed
__device__ ull     g_mpk[NN];         // (f32bits(d_pos)<<32)|sorted_idx
__device__ int     g_order[NN];
__device__ int     g_scls[NN];
__device__ float   g_sx2[NN];
__device__ int     g_cstart[NC];
__device__ int     g_count[NC];
__device__ __half2 g_Eh[NN][64];      // sorted rows, k-contiguous fp16

__device__ __forceinline__ uint32_t smem_u32(const void* p) {
    uint32_t a;
    asm("{ .reg .u64 t; cvta.to.shared.u64 t, %1; cvt.u32.u64 %0, t; }" : "=r"(a) : "l"(p));
    return a;
}

#define LDSM4(r0, r1, r2, r3, addr)                                          \
    asm volatile("ldmatrix.sync.aligned.m8n8.x4.shared.b16 {%0,%1,%2,%3},[%4];" \
        : "=r"(r0), "=r"(r1), "=r"(r2), "=r"(r3) : "r"(addr))

#define MMA16816(cp, a0, a1, a2, a3, b0, b1)                                 \
    asm volatile("mma.sync.aligned.m16n8k16.row.col.f32.f16.f16.f32 "        \
        "{%0,%1,%2,%3},{%4,%5,%6,%7},{%8,%9},{%0,%1,%2,%3};"                 \
        : "+f"((cp)[0]), "+f"((cp)[1]), "+f"((cp)[2]), "+f"((cp)[3])         \
        : "r"(a0), "r"(a1), "r"(a2), "r"(a3), "r"(b0), "r"(b1))

// ---------------------------------------------------------------------------
// Kernel 1: parallel stable (class,index) sort. 1 block, 1024 threads.
// ---------------------------------------------------------------------------
__global__ __launch_bounds__(1024)
void bh_table(const int* __restrict__ labels)
{
    __shared__ int wpre[32][NC];      // warp totals -> exclusive prefix
    __shared__ int lofs[1024][NC];    // per-lane exclusive offsets (dyn-indexed)
    __shared__ int cst[NC];

    const int tid  = threadIdx.x;
    const int w    = tid >> 5;
    const int lane = tid & 31;
    const int base = tid * 8;

    int4 l0 = *reinterpret_cast<const int4*>(labels + base);
    int4 l1 = *reinterpret_cast<const int4*>(labels + base + 4);
    int lab[8] = {l0.x, l0.y, l0.z, l0.w, l1.x, l1.y, l1.z, l1.w};

    int lc[NC];
#pragma unroll
    for (int c = 0; c < NC; c++) lc[c] = 0;
#pragma unroll
    for (int i = 0; i < 8; i++)
#pragma unroll
        for (int c = 0; c < NC; c++) lc[c] += (lab[i] == c);

#pragma unroll
    for (int c = 0; c < NC; c++) {
        int v = lc[c], inc = v;
#pragma unroll
        for (int off = 1; off < 32; off <<= 1) {
            int o = __shfl_up_sync(0xffffffffu, inc, off);
            if (lane >= off) inc += o;
        }
        lofs[tid][c] = inc - v;
        if (lane == 31) wpre[w][c] = inc;
    }
    __syncthreads();

    if (tid < NC) {
        int run = 0;
        for (int t = 0; t < 32; t++) { int tmp = wpre[t][tid]; wpre[t][tid] = run; run += tmp; }
        g_count[tid] = run;
    }
    __syncthreads();
    if (tid == 0) {
        int run = 0;
        for (int c = 0; c < NC; c++) { cst[c] = run; g_cstart[c] = run; run += g_count[c]; }
    }
    __syncthreads();

#pragma unroll
    for (int i = 0; i < 8; i++) {
        int c = lab[i];
        int rk = 0;
#pragma unroll
        for (int j = 0; j < 8; j++) rk += (j < i) && (lab[j] == c);
        int pos = cst[c] + wpre[w][c] + lofs[tid][c] + rk;
        g_order[pos] = base + i;
        g_scls[pos]  = c;
    }
}

// ---------------------------------------------------------------------------
// Kernel 2: pack sorted rows to fp16, compute norms, zero stats + out.
// ---------------------------------------------------------------------------
__global__ void bh_pack(const float* __restrict__ E, float* __restrict__ out)
{
    const int p    = (blockIdx.x * blockDim.x + threadIdx.x) >> 5;
    const int lane = threadIdx.x & 31;
    if (blockIdx.x == 0 && threadIdx.x == 0) out[0] = 0.0f;

    const int gi = g_order[p];
    float4 v = *reinterpret_cast<const float4*>(E + (size_t)gi * DD + lane * 4);
    g_Eh[p][lane * 2]     = __floats2half2_rn(v.x, v.y);
    g_Eh[p][lane * 2 + 1] = __floats2half2_rn(v.z, v.w);

    float s = v.x * v.x + v.y * v.y + v.z * v.z + v.w * v.w;
#pragma unroll
    for (int off = 16; off >= 1; off >>= 1)
        s += __shfl_xor_sync(0xffffffffu, s, off);
    if (lane == 0) { g_x2[gi] = s; g_sx2[p] = s; g_mpk[p] = 0ull; }
    if (lane < NC) g_S[p][lane] = 0.f;
}

// ---------------------------------------------------------------------------
// Kernel 3: symmetric-tile Gram via HMMA, 32x64 warp tiles, fragment-domain
// row stats, single-read col pass over the clamped-d dump.
// ---------------------------------------------------------------------------
__global__ __launch_bounds__(256, 2)
void bh_main()
{
    extern __shared__ char smraw[];
    const uint32_t sb = smem_u32(smraw);
    __half* Ah  = (__half*)smraw;                // [128][PITCH]
    float*  ds  = (float*)smraw;                 // [128][DPITCH], reuses tiles
    float*  sxj = (float*)(smraw + 69632);       // [128] col norms
    float*  sxr = sxj + 128;                     // [128] row norms
    __shared__ int sb_col, sb_row;

    const int tid  = threadIdx.x;
    const int w    = tid >> 5;
    const int lane = tid & 31;
    const int g    = lane >> 2, t = lane & 3;
    const int wr   = w & 3, wc = w >> 2;

    // triangular decode
    const float bf = (float)blockIdx.x;
    int bi = (int)(63.5f - sqrtf(fmaxf(63.5f * 63.5f - 2.0f * bf + 0.25f, 0.0f)));
    while ((bi + 1) * NB - ((bi + 1) * bi) / 2 <= (int)blockIdx.x) ++bi;
    while (bi * NB - (bi * (bi - 1)) / 2 > (int)blockIdx.x) --bi;
    const int bj = bi + ((int)blockIdx.x - (bi * NB - (bi * (bi - 1)) / 2));
    const bool diag = (bi == bj);
    const int rowbase = bi * BT;
    const int jbase   = bj * BT;

    if (tid == 0) { sb_col = BT; sb_row = BT; }
    __syncthreads();
    if (tid < BT - 1) {
        if (g_scls[jbase + tid + 1]   != g_scls[jbase + tid])   atomicMin(&sb_col, tid + 1);
        if (g_scls[rowbase + tid + 1] != g_scls[rowbase + tid]) atomicMin(&sb_row, tid + 1);
    }

    // ---- tile loads ----
#pragma unroll
    for (int it = 0; it < 8; ++it) {
        int idx = tid + it * 256;
        int row = idx >> 4, c = idx & 15;
        uint4 v = *reinterpret_cast<const uint4*>(
            reinterpret_cast<const char*>(&g_Eh[rowbase + row][0]) + c * 16);
        *reinterpret_cast<uint4*>(Ah + row * PITCH + c * 8) = v;
    }
    if (!diag) {
        __half* Bh = Ah + 128 * PITCH;
#pragma unroll
        for (int it = 0; it < 8; ++it) {
            int idx = tid + it * 256;
            int row = idx >> 4, c = idx & 15;
            uint4 v = *reinterpret_cast<const uint4*>(
                reinterpret_cast<const char*>(&g_Eh[jbase + row][0]) + c * 16);
            *reinterpret_cast<uint4*>(Bh + row * PITCH + c * 8) = v;
        }
    }
    if (tid < BT) { sxj[tid] = g_sx2[jbase + tid]; sxr[tid] = g_sx2[rowbase + tid]; }
    __syncthreads();

    // ---- MMA mainloop: warp tile 32 rows x 64 cols ----
    const uint32_t aBase0 = sb + ((wr * 32 + (lane & 15)) * PITCH + ((lane >> 4) << 3)) * 2;
    const uint32_t aBase1 = aBase0 + 16 * PITCH * 2;
    const uint32_t bTile  = diag ? sb : (sb + 128 * PITCH * 2);
    const uint32_t bBase  = bTile + ((wc * 64 + (lane & 7) + ((lane >> 4) << 3)) * PITCH
                                     + (((lane >> 3) & 1) << 3)) * 2;

    float cfr[2][8][4];
#pragma unroll
    for (int mi = 0; mi < 2; ++mi)
#pragma unroll
        for (int n = 0; n < 8; ++n)
#pragma unroll
            for (int q = 0; q < 4; ++q) cfr[mi][n][q] = 0.f;

#pragma unroll
    for (int ks = 0; ks < 8; ++ks) {
        uint32_t a00, a01, a02, a03, a10, a11, a12, a13;
        LDSM4(a00, a01, a02, a03, aBase0 + ks * 32);
        LDSM4(a10, a11, a12, a13, aBase1 + ks * 32);
#pragma unroll
        for (int np = 0; np < 4; ++np) {
            uint32_t b0, b1, b2, b3;
            LDSM4(b0, b1, b2, b3, bBase + np * (16 * PITCH * 2) + ks * 32);
            MMA16816(cfr[0][np * 2],     a00, a01, a02, a03, b0, b1);
            MMA16816(cfr[0][np * 2 + 1], a00, a01, a02, a03, b2, b3);
            MMA16816(cfr[1][np * 2],     a10, a11, a12, a13, b0, b1);
            MMA16816(cfr[1][np * 2 + 1], a10, a11, a12, a13, b2, b3);
        }
    }
    __syncthreads();   // all tile reads done; safe to overwrite with d

    const int scol = sb_col, srow = sb_row;
    const int cAc = g_scls[jbase],   cBc = g_scls[jbase + BT - 1];
    const int cAr = g_scls[rowbase], cBr = g_scls[rowbase + BT - 1];

    // ---- fragment-domain epilogue: compute d once, row stats + dump ----
    int   rowt[2][2], rcv[2][2];
    float xrv[2][2], sA[2][2], sBv[2][2], mv[2][2];
    int   mc[2][2];
#pragma unroll
    for (int mi = 0; mi < 2; ++mi)
#pragma unroll
        for (int h = 0; h < 2; ++h) {
            rowt[mi][h] = wr * 32 + mi * 16 + g + h * 8;
            xrv[mi][h]  = sxr[rowt[mi][h]];
            rcv[mi][h]  = (rowt[mi][h] < srow) ? cAr : cBr;
            sA[mi][h] = 0.f; sBv[mi][h] = 0.f; mv[mi][h] = -1.f; mc[mi][h] = 0;
        }

#pragma unroll
    for (int n = 0; n < 8; ++n) {
        const int  c0  = wc * 64 + n * 8 + t * 2;
        const float xj0 = sxj[c0], xj1 = sxj[c0 + 1];
        const bool a0 = c0 < scol, a1 = (c0 + 1) < scol;
        const int  cc0 = a0 ? cAc : cBc, cc1 = a1 ? cAc : cBc;
#pragma unroll
        for (int mi = 0; mi < 2; ++mi)
#pragma unroll
            for (int h = 0; h < 2; ++h) {
                float d0 = fmaxf(fmaf(-2.0f, cfr[mi][n][h * 2],     xrv[mi][h] + xj0), 0.0f);
                float d1 = fmaxf(fmaf(-2.0f, cfr[mi][n][h * 2 + 1], xrv[mi][h] + xj1), 0.0f);
                if (a0) sA[mi][h] += d0; else sBv[mi][h] += d0;
                if (a1) sA[mi][h] += d1; else sBv[mi][h] += d1;
                if (cc0 == rcv[mi][h] && d0 > mv[mi][h]) { mv[mi][h] = d0; mc[mi][h] = c0; }
                if (cc1 == rcv[mi][h] && d1 > mv[mi][h]) { mv[mi][h] = d1; mc[mi][h] = c0 + 1; }
                ds[rowt[mi][h] * DPITCH + c0]     = d0;
                ds[rowt[mi][h] * DPITCH + c0 + 1] = d1;
            }
    }

    // row-side reduce across the 4 t-lanes, publish at t==0
#pragma unroll
    for (int off = 2; off >= 1; off >>= 1) {
#pragma unroll
        for (int mi = 0; mi < 2; ++mi)
#pragma unroll
            for (int h = 0; h < 2; ++h) {
                sA[mi][h]  += __shfl_down_sync(0xffffffffu, sA[mi][h],  off, 4);
                sBv[mi][h] += __shfl_down_sync(0xffffffffu, sBv[mi][h], off, 4);
                float ov = __shfl_down_sync(0xffffffffu, mv[mi][h], off, 4);
                int   oc = __shfl_down_sync(0xffffffffu, mc[mi][h], off, 4);
                if (ov > mv[mi][h]) { mv[mi][h] = ov; mc[mi][h] = oc; }
            }
    }
    if (t == 0) {
#pragma unroll
        for (int mi = 0; mi < 2; ++mi)
#pragma unroll
            for (int h = 0; h < 2; ++h) {
                const int rp = rowbase + rowt[mi][h];
                atomicAdd(&g_S[rp][cAc], sA[mi][h]);
                if (scol < BT) atomicAdd(&g_S[rp][cBc], sBv[mi][h]);
                if (mv[mi][h] >= 0.f)
                    atomicMax(&g_mpk[rp], (((ull)__float_as_uint(mv[mi][h])) << 32)
                                          | (unsigned)(jbase + mc[mi][h]));
            }
    }
    __syncthreads();

    // ---- col pass: read clamped d once (off-diagonal only) ----
    if (!diag) {
        const int col = tid >> 1, half = tid & 1;
        const int cc  = (col < scol) ? cAc : cBc;
        float sAc = 0.f, sBc = 0.f, mvc = -1.f;
        int   mrc = 0;
#pragma unroll 8
        for (int rr = 0; rr < 64; ++rr) {
            const int row = half * 64 + ((rr + half * 4) & 63);   // bank stagger
            float d = ds[row * DPITCH + col];
            const bool isA = row < srow;
            if (isA) sAc += d; else sBc += d;
            if (((isA) ? cAr : cBr) == cc && d > mvc) { mvc = d; mrc = row; }
        }
        sAc += __shfl_down_sync(0xffffffffu, sAc, 1, 2);
        sBc += __shfl_down_sync(0xffffffffu, sBc, 1, 2);
        float ov = __shfl_down_sync(0xffffffffu, mvc, 1, 2);
        int   orr = __shfl_down_sync(0xffffffffu, mrc, 1, 2);
        if (ov > mvc) { mvc = ov; mrc = orr; }
        if (half == 0) {
            const int cp = jbase + col;
            atomicAdd(&g_S[cp][cAr], sAc);
            if (srow < BT) atomicAdd(&g_S[cp][cBr], sBc);
            if (mvc >= 0.f)
                atomicMax(&g_mpk[cp], (((ull)__float_as_uint(mvc)) << 32)
                                      | (unsigned)(rowbase + mrc));
        }
    }
}

// ---------------------------------------------------------------------------
// Kernel 4: finalize — warp per sorted anchor: argmin, class walk,
// EXACT fp32 recompute of d_pos (tracked argmax) and d_neg.
// ---------------------------------------------------------------------------
__global__ void bh_final(const float* __restrict__ E, float* __restrict__ out)
{
    const int p    = (blockIdx.x * blockDim.x + threadIdx.x) >> 5;
    const int lane = threadIdx.x & 31;

    float T = 0.f, S[NC];
#pragma unroll
    for (int c = 0; c < NC; c++) { S[c] = g_S[p][c]; T += S[c]; }

    float best = 3.4e38f;
    int   ks   = 0;
#pragma unroll
    for (int c = 0; c < NC; c++) {
        float nd = T - S[c];
        if (nd < best) { best = nd; ks = c; }
    }

    const int la = g_scls[p];
    int rem = ks, js = 0;
#pragma unroll
    for (int c = 0; c < NC; c++) {
        if (c == la) continue;
        int cn = g_count[c];
        if (rem < cn) { js = g_order[g_cstart[c] + rem]; rem = 0x7fffffff; }
        else rem -= cn;
    }

    const ull key = g_mpk[p];
    const int jpq = (int)(key & 0xffffffffu);
    const int gjp = g_order[jpq];
    const int gi  = g_order[p];

    float4 a  = *reinterpret_cast<const float4*>(E + (size_t)gi  * DD + lane * 4);
    float4 bp = *reinterpret_cast<const float4*>(E + (size_t)gjp * DD + lane * 4);
    float4 bn = *reinterpret_cast<const float4*>(E + (size_t)js  * DD + lane * 4);
    float dotp = a.x * bp.x + a.y * bp.y + a.z * bp.z + a.w * bp.w;
    float dotn = a.x * bn.x + a.y * bn.y + a.z * bn.z + a.w * bn.w;
#pragma unroll
    for (int off = 16; off >= 1; off >>= 1) {
        dotp += __shfl_xor_sync(0xffffffffu, dotp, off);
        dotn += __shfl_xor_sync(0xffffffffu, dotn, off);
    }

    float loss = 0.f;
    if (lane == 0) {
        float dp = fmaxf(g_x2[gi] + g_x2[gjp] - 2.0f * dotp, 0.0f);
        float dn = fmaxf(g_x2[gi] + g_x2[js]  - 2.0f * dotn, 0.0f);
        loss = fmaxf(dp - dn + 1.0f, 0.0f);
    }

    __shared__ float wsum[8];
    if (lane == 0) wsum[threadIdx.x >> 5] = loss;
    __syncthreads();
    if (threadIdx.x == 0) {
        float s = 0.f;
#pragma unroll
        for (int w = 0; w < 8; w++) s += wsum[w];
        atomicAdd(out, s * (1.0f / NN));
    }
}

// ---------------------------------------------------------------------------
extern "C" void kernel_launch(void* const* d_in, const int* in_sizes, int n_in,
                              void* d_out, int out_size)
{
    const float* E      = (const float*)d_in[0];
    const int*   labels = (const int*)d_in[1];
    float*       out    = (float*)d_out;

    const int smem = 69632 + 2 * 128 * 4;   // tiles (reused as d) + sxj + sxr
    cudaFuncSetAttribute(bh_main, cudaFuncAttributeMaxDynamicSharedMemorySize, smem);

    bh_table<<<1, 1024>>>(labels);
    bh_pack<<<NN * 32 / 256, 256>>>(E, out);
    bh_main<<<NTILES, 256, smem>>>();
    bh_final<<<NN * 32 / 256, 256>>>(E, out);
}

// round 12
// speedup vs baseline: 4.1476x; 1.0279x over previous
#include <cuda_runtime.h>
#include <cuda_fp16.h>
#include <cstdint>

#define NN 8192
#define DD 128
#define NC 10
#define BT 128
#define NB (NN / BT)
#define NTILES (NB * (NB + 1) / 2)   // 2080
#define PITCH 136                     // halves per smem tile row
#define DP2 68                        // half2 per d-matrix row

typedef unsigned long long ull;

// ---- device globals ----
__device__ float   g_x2[NN];
__device__ float   g_S[NN][NC];       // sorted-position indexed
__device__ ull     g_mpk[NN];         // (f32bits(d_pos)<<32)|sorted_idx
__device__ int     g_order[NN];
__device__ int     g_scls[NN];
__device__ float   g_sx2[NN];
__device__ int     g_cstart[NC];
__device__ int     g_count[NC];
__device__ __half2 g_Eh[NN][64];      // sorted rows, k-contiguous fp16

__device__ __forceinline__ uint32_t smem_u32(const void* p) {
    uint32_t a;
    asm("{ .reg .u64 t; cvta.to.shared.u64 t, %1; cvt.u32.u64 %0, t; }" : "=r"(a) : "l"(p));
    return a;
}

#define LDSM4(r0, r1, r2, r3, addr)                                          \
    asm volatile("ldmatrix.sync.aligned.m8n8.x4.shared.b16 {%0,%1,%2,%3},[%4];" \
        : "=r"(r0), "=r"(r1), "=r"(r2), "=r"(r3) : "r"(addr))

#define MMA16816(cp, a0, a1, a2, a3, b0, b1)                                 \
    asm volatile("mma.sync.aligned.m16n8k16.row.col.f32.f16.f16.f32 "        \
        "{%0,%1,%2,%3},{%4,%5,%6,%7},{%8,%9},{%0,%1,%2,%3};"                 \
        : "+f"((cp)[0]), "+f"((cp)[1]), "+f"((cp)[2]), "+f"((cp)[3])         \
        : "r"(a0), "r"(a1), "r"(a2), "r"(a3), "r"(b0), "r"(b1))

// ---------------------------------------------------------------------------
// Kernel 1: parallel stable (class,index) sort. 1 block, 1024 threads.
// ---------------------------------------------------------------------------
__global__ __launch_bounds__(1024)
void bh_table(const int* __restrict__ labels)
{
    __shared__ int wpre[32][NC];
    __shared__ int lofs[1024][NC];
    __shared__ int cst[NC];

    const int tid  = threadIdx.x;
    const int w    = tid >> 5;
    const int lane = tid & 31;
    const int base = tid * 8;

    int4 l0 = *reinterpret_cast<const int4*>(labels + base);
    int4 l1 = *reinterpret_cast<const int4*>(labels + base + 4);
    int lab[8] = {l0.x, l0.y, l0.z, l0.w, l1.x, l1.y, l1.z, l1.w};

    int lc[NC];
#pragma unroll
    for (int c = 0; c < NC; c++) lc[c] = 0;
#pragma unroll
    for (int i = 0; i < 8; i++)
#pragma unroll
        for (int c = 0; c < NC; c++) lc[c] += (lab[i] == c);

#pragma unroll
    for (int c = 0; c < NC; c++) {
        int v = lc[c], inc = v;
#pragma unroll
        for (int off = 1; off < 32; off <<= 1) {
            int o = __shfl_up_sync(0xffffffffu, inc, off);
            if (lane >= off) inc += o;
        }
        lofs[tid][c] = inc - v;
        if (lane == 31) wpre[w][c] = inc;
    }
    __syncthreads();

    if (tid < NC) {
        int run = 0;
        for (int t = 0; t < 32; t++) { int tmp = wpre[t][tid]; wpre[t][tid] = run; run += tmp; }
        g_count[tid] = run;
    }
    __syncthreads();
    if (tid == 0) {
        int run = 0;
        for (int c = 0; c < NC; c++) { cst[c] = run; g_cstart[c] = run; run += g_count[c]; }
    }
    __syncthreads();

#pragma unroll
    for (int i = 0; i < 8; i++) {
        int c = lab[i];
        int rk = 0;
#pragma unroll
        for (int j = 0; j < 8; j++) rk += (j < i) && (lab[j] == c);
        int pos = cst[c] + wpre[w][c] + lofs[tid][c] + rk;
        g_order[pos] = base + i;
        g_scls[pos]  = c;
    }
}

// ---------------------------------------------------------------------------
// Kernel 2: pack sorted rows to fp16, compute norms, zero stats + out.
// ---------------------------------------------------------------------------
__global__ void bh_pack(const float* __restrict__ E, float* __restrict__ out)
{
    const int p    = (blockIdx.x * blockDim.x + threadIdx.x) >> 5;
    const int lane = threadIdx.x & 31;
    if (blockIdx.x == 0 && threadIdx.x == 0) out[0] = 0.0f;

    const int gi = g_order[p];
    float4 v = *reinterpret_cast<const float4*>(E + (size_t)gi * DD + lane * 4);
    g_Eh[p][lane * 2]     = __floats2half2_rn(v.x, v.y);
    g_Eh[p][lane * 2 + 1] = __floats2half2_rn(v.z, v.w);

    float s = v.x * v.x + v.y * v.y + v.z * v.z + v.w * v.w;
#pragma unroll
    for (int off = 16; off >= 1; off >>= 1)
        s += __shfl_xor_sync(0xffffffffu, s, off);
    if (lane == 0) { g_x2[gi] = s; g_sx2[p] = s; g_mpk[p] = 0ull; }
    if (lane < NC) g_S[p][lane] = 0.f;
}

// ---------------------------------------------------------------------------
// Kernel 3: symmetric-tile Gram via HMMA, fragment-domain row stats,
// fp16 d-matrix for the col pass (half the crossbar traffic of fp32).
// ---------------------------------------------------------------------------
__global__ __launch_bounds__(256, 2)
void bh_main()
{
    extern __shared__ char smraw[];
    const uint32_t sb = smem_u32(smraw);
    __half*  Ah  = (__half*)smraw;                 // [128][PITCH]
    __half2* dsh = (__half2*)smraw;                // [128][DP2], reuses tiles
    float*   qA  = (float*)(smraw + 128 * DP2 * 4);// [4][128]
    float*   qB  = qA + 512;                       // [4][128]
    float*   qV  = qB + 512;                       // [4][128]
    int*     qR  = (int*)(qV + 512);               // [4][128]
    float*   sxj = (float*)(smraw + 69632);        // [128] col norms
    float*   sxr = sxj + 128;                      // [128] row norms
    __shared__ int sb_col, sb_row;

    const int tid  = threadIdx.x;
    const int w    = tid >> 5;
    const int lane = tid & 31;
    const int g    = lane >> 2, t = lane & 3;
    const int wr   = w & 3, wc = w >> 2;

    // triangular decode
    const float bf = (float)blockIdx.x;
    int bi = (int)(63.5f - sqrtf(fmaxf(63.5f * 63.5f - 2.0f * bf + 0.25f, 0.0f)));
    while ((bi + 1) * NB - ((bi + 1) * bi) / 2 <= (int)blockIdx.x) ++bi;
    while (bi * NB - (bi * (bi - 1)) / 2 > (int)blockIdx.x) --bi;
    const int bj = bi + ((int)blockIdx.x - (bi * NB - (bi * (bi - 1)) / 2));
    const bool diag = (bi == bj);
    const int rowbase = bi * BT;
    const int jbase   = bj * BT;

    if (tid == 0) { sb_col = BT; sb_row = BT; }
    __syncthreads();
    if (tid < BT - 1) {
        if (g_scls[jbase + tid + 1]   != g_scls[jbase + tid])   atomicMin(&sb_col, tid + 1);
        if (g_scls[rowbase + tid + 1] != g_scls[rowbase + tid]) atomicMin(&sb_row, tid + 1);
    }

    // ---- tile loads ----
#pragma unroll
    for (int it = 0; it < 8; ++it) {
        int idx = tid + it * 256;
        int row = idx >> 4, c = idx & 15;
        uint4 v = *reinterpret_cast<const uint4*>(
            reinterpret_cast<const char*>(&g_Eh[rowbase + row][0]) + c * 16);
        *reinterpret_cast<uint4*>(Ah + row * PITCH + c * 8) = v;
    }
    if (!diag) {
        __half* Bh = Ah + 128 * PITCH;
#pragma unroll
        for (int it = 0; it < 8; ++it) {
            int idx = tid + it * 256;
            int row = idx >> 4, c = idx & 15;
            uint4 v = *reinterpret_cast<const uint4*>(
                reinterpret_cast<const char*>(&g_Eh[jbase + row][0]) + c * 16);
            *reinterpret_cast<uint4*>(Bh + row * PITCH + c * 8) = v;
        }
    }
    if (tid < BT) { sxj[tid] = g_sx2[jbase + tid]; sxr[tid] = g_sx2[rowbase + tid]; }
    __syncthreads();

    // ---- MMA mainloop: warp tile 32 rows x 64 cols ----
    const uint32_t aBase0 = sb + ((wr * 32 + (lane & 15)) * PITCH + ((lane >> 4) << 3)) * 2;
    const uint32_t aBase1 = aBase0 + 16 * PITCH * 2;
    const uint32_t bTile  = diag ? sb : (sb + 128 * PITCH * 2);
    const uint32_t bBase  = bTile + ((wc * 64 + (lane & 7) + ((lane >> 4) << 3)) * PITCH
                                     + (((lane >> 3) & 1) << 3)) * 2;

    float cfr[2][8][4];
#pragma unroll
    for (int mi = 0; mi < 2; ++mi)
#pragma unroll
        for (int n = 0; n < 8; ++n)
#pragma unroll
            for (int q = 0; q < 4; ++q) cfr[mi][n][q] = 0.f;

#pragma unroll
    for (int ks = 0; ks < 8; ++ks) {
        uint32_t a00, a01, a02, a03, a10, a11, a12, a13;
        LDSM4(a00, a01, a02, a03, aBase0 + ks * 32);
        LDSM4(a10, a11, a12, a13, aBase1 + ks * 32);
#pragma unroll
        for (int np = 0; np < 4; ++np) {
            uint32_t b0, b1, b2, b3;
            LDSM4(b0, b1, b2, b3, bBase + np * (16 * PITCH * 2) + ks * 32);
            MMA16816(cfr[0][np * 2],     a00, a01, a02, a03, b0, b1);
            MMA16816(cfr[0][np * 2 + 1], a00, a01, a02, a03, b2, b3);
            MMA16816(cfr[1][np * 2],     a10, a11, a12, a13, b0, b1);
            MMA16816(cfr[1][np * 2 + 1], a10, a11, a12, a13, b2, b3);
        }
    }
    __syncthreads();   // all tile reads done; safe to overwrite with d

    const int scol = sb_col, srow = sb_row;
    const int cAc = g_scls[jbase],   cBc = g_scls[jbase + BT - 1];
    const int cAr = g_scls[rowbase], cBr = g_scls[rowbase + BT - 1];

    // ---- fragment-domain epilogue: d once, exact fp32 row stats, fp16 dump
    int   rowt[2][2], rcv[2][2];
    float xrv[2][2], sA[2][2], sBv[2][2], mv[2][2];
    int   mc[2][2];
#pragma unroll
    for (int mi = 0; mi < 2; ++mi)
#pragma unroll
        for (int h = 0; h < 2; ++h) {
            rowt[mi][h] = wr * 32 + mi * 16 + g + h * 8;
            xrv[mi][h]  = sxr[rowt[mi][h]];
            rcv[mi][h]  = (rowt[mi][h] < srow) ? cAr : cBr;
            sA[mi][h] = 0.f; sBv[mi][h] = 0.f; mv[mi][h] = -1.f; mc[mi][h] = 0;
        }

#pragma unroll
    for (int n = 0; n < 8; ++n) {
        const int  c0  = wc * 64 + n * 8 + t * 2;
        const float xj0 = sxj[c0], xj1 = sxj[c0 + 1];
        const bool a0 = c0 < scol, a1 = (c0 + 1) < scol;
        const int  cc0 = a0 ? cAc : cBc, cc1 = a1 ? cAc : cBc;
#pragma unroll
        for (int mi = 0; mi < 2; ++mi)
#pragma unroll
            for (int h = 0; h < 2; ++h) {
                float d0 = fmaxf(fmaf(-2.0f, cfr[mi][n][h * 2],     xrv[mi][h] + xj0), 0.0f);
                float d1 = fmaxf(fmaf(-2.0f, cfr[mi][n][h * 2 + 1], xrv[mi][h] + xj1), 0.0f);
                if (a0) sA[mi][h] += d0; else sBv[mi][h] += d0;
                if (a1) sA[mi][h] += d1; else sBv[mi][h] += d1;
                if (cc0 == rcv[mi][h] && d0 > mv[mi][h]) { mv[mi][h] = d0; mc[mi][h] = c0; }
                if (cc1 == rcv[mi][h] && d1 > mv[mi][h]) { mv[mi][h] = d1; mc[mi][h] = c0 + 1; }
                if (!diag)
                    dsh[rowt[mi][h] * DP2 + (c0 >> 1)] = __floats2half2_rn(d0, d1);
            }
    }

    // row-side reduce across the 4 t-lanes, publish at t==0
#pragma unroll
    for (int off = 2; off >= 1; off >>= 1) {
#pragma unroll
        for (int mi = 0; mi < 2; ++mi)
#pragma unroll
            for (int h = 0; h < 2; ++h) {
                sA[mi][h]  += __shfl_down_sync(0xffffffffu, sA[mi][h],  off, 4);
                sBv[mi][h] += __shfl_down_sync(0xffffffffu, sBv[mi][h], off, 4);
                float ov = __shfl_down_sync(0xffffffffu, mv[mi][h], off, 4);
                int   oc = __shfl_down_sync(0xffffffffu, mc[mi][h], off, 4);
                if (ov > mv[mi][h]) { mv[mi][h] = ov; mc[mi][h] = oc; }
            }
    }
    if (t == 0) {
#pragma unroll
        for (int mi = 0; mi < 2; ++mi)
#pragma unroll
            for (int h = 0; h < 2; ++h) {
                const int rp = rowbase + rowt[mi][h];
                atomicAdd(&g_S[rp][cAc], sA[mi][h]);
                if (scol < BT) atomicAdd(&g_S[rp][cBc], sBv[mi][h]);
                if (mv[mi][h] >= 0.f)
                    atomicMax(&g_mpk[rp], (((ull)__float_as_uint(mv[mi][h])) << 32)
                                          | (unsigned)(jbase + mc[mi][h]));
            }
    }

    // ---- col pass over fp16 d: 2 cols/thread x 32 rows (off-diag only) ----
    if (!diag) {
        __syncthreads();
        const int cp = tid & 63, q = tid >> 6;
        const int c0 = cp * 2, c1 = c0 + 1;
        const int cc0 = (c0 < scol) ? cAc : cBc;
        const int cc1 = (c1 < scol) ? cAc : cBc;
        float s0A = 0.f, s0B = 0.f, s1A = 0.f, s1B = 0.f;
        float m0 = -1.f, m1 = -1.f;
        int   r0 = 0, r1 = 0;
#pragma unroll 8
        for (int rr = 0; rr < 32; ++rr) {
            const int row = q * 32 + rr;
            float2 d = __half22float2(dsh[row * DP2 + cp]);
            const bool isA = row < srow;
            const int  rc  = isA ? cAr : cBr;
            if (isA) { s0A += d.x; s1A += d.y; } else { s0B += d.x; s1B += d.y; }
            if (rc == cc0 && d.x > m0) { m0 = d.x; r0 = row; }
            if (rc == cc1 && d.y > m1) { m1 = d.y; r1 = row; }
        }
        qA[q * 128 + c0] = s0A;  qA[q * 128 + c1] = s1A;
        qB[q * 128 + c0] = s0B;  qB[q * 128 + c1] = s1B;
        qV[q * 128 + c0] = m0;   qV[q * 128 + c1] = m1;
        qR[q * 128 + c0] = r0;   qR[q * 128 + c1] = r1;
        __syncthreads();

        if (tid < BT) {
            const int col = tid;
            float sAc = 0.f, sBc = 0.f, mvc = -1.f;
            int   mrc = 0;
#pragma unroll
            for (int qq = 0; qq < 4; ++qq) {
                sAc += qA[qq * 128 + col];
                sBc += qB[qq * 128 + col];
                float v = qV[qq * 128 + col];
                if (v > mvc) { mvc = v; mrc = qR[qq * 128 + col]; }
            }
            const int cpo = jbase + col;
            atomicAdd(&g_S[cpo][cAr], sAc);
            if (srow < BT) atomicAdd(&g_S[cpo][cBr], sBc);
            if (mvc >= 0.f)
                atomicMax(&g_mpk[cpo], (((ull)__float_as_uint(mvc)) << 32)
                                       | (unsigned)(rowbase + mrc));
        }
    }
}

// ---------------------------------------------------------------------------
// Kernel 4: finalize — warp per sorted anchor: argmin, class walk,
// EXACT fp32 recompute of d_pos (tracked argmax) and d_neg.
// ---------------------------------------------------------------------------
__global__ void bh_final(const float* __restrict__ E, float* __restrict__ out)
{
    const int p    = (blockIdx.x * blockDim.x + threadIdx.x) >> 5;
    const int lane = threadIdx.x & 31;

    float T = 0.f, S[NC];
#pragma unroll
    for (int c = 0; c < NC; c++) { S[c] = g_S[p][c]; T += S[c]; }

    float best = 3.4e38f;
    int   ks   = 0;
#pragma unroll
    for (int c = 0; c < NC; c++) {
        float nd = T - S[c];
        if (nd < best) { best = nd; ks = c; }
    }

    const int la = g_scls[p];
    int rem = ks, js = 0;
#pragma unroll
    for (int c = 0; c < NC; c++) {
        if (c == la) continue;
        int cn = g_count[c];
        if (rem < cn) { js = g_order[g_cstart[c] + rem]; rem = 0x7fffffff; }
        else rem -= cn;
    }

    const ull key = g_mpk[p];
    const int jpq = (int)(key & 0xffffffffu);
    const int gjp = g_order[jpq];
    const int gi  = g_order[p];

    float4 a  = *reinterpret_cast<const float4*>(E + (size_t)gi  * DD + lane * 4);
    float4 bp = *reinterpret_cast<const float4*>(E + (size_t)gjp * DD + lane * 4);
    float4 bn = *reinterpret_cast<const float4*>(E + (size_t)js  * DD + lane * 4);
    float dotp = a.x * bp.x + a.y * bp.y + a.z * bp.z + a.w * bp.w;
    float dotn = a.x * bn.x + a.y * bn.y + a.z * bn.z + a.w * bn.w;
#pragma unroll
    for (int off = 16; off >= 1; off >>= 1) {
        dotp += __shfl_xor_sync(0xffffffffu, dotp, off);
        dotn += __shfl_xor_sync(0xffffffffu, dotn, off);
    }

    float loss = 0.f;
    if (lane == 0) {
        float dp = fmaxf(g_x2[gi] + g_x2[gjp] - 2.0f * dotp, 0.0f);
        float dn = fmaxf(g_x2[gi] + g_x2[js]  - 2.0f * dotn, 0.0f);
        loss = fmaxf(dp - dn + 1.0f, 0.0f);
    }

    __shared__ float wsum[8];
    if (lane == 0) wsum[threadIdx.x >> 5] = loss;
    __syncthreads();
    if (threadIdx.x == 0) {
        float s = 0.f;
#pragma unroll
        for (int w = 0; w < 8; w++) s += wsum[w];
        atomicAdd(out, s * (1.0f / NN));
    }
}

// ---------------------------------------------------------------------------
extern "C" void kernel_launch(void* const* d_in, const int* in_sizes, int n_in,
                              void* d_out, int out_size)
{
    const float* E      = (const float*)d_in[0];
    const int*   labels = (const int*)d_in[1];
    float*       out    = (float*)d_out;

    const int smem = 69632 + 2 * 128 * 4;   // tiles (reused as d + partials) + sxj + sxr
    cudaFuncSetAttribute(bh_main, cudaFuncAttributeMaxDynamicSharedMemorySize, smem);

    bh_table<<<1, 1024>>>(labels);
    bh_pack<<<NN * 32 / 256, 256>>>(E, out);
    bh_main<<<NTILES, 256, smem>>>();
    bh_final<<<NN * 32 / 256, 256>>>(E, out);
}

// round 13
// speedup vs baseline: 4.5181x; 1.0893x over previous
#include <cuda_runtime.h>
#include <cuda_fp16.h>
#include <cstdint>

#define NN 8192
#define DD 128
#define NC 10
#define BT 128
#define NB (NN / BT)
#define NOFF (NB * (NB - 1) / 2)     // 2016 off-diag tiles
#define NTILES (NOFF + NB)            // + 64 diag
#define PITCH 136
#define DP2 68

typedef unsigned long long ull;

__device__ float   g_x2[NN];
__device__ float   g_S[NN][NC];
__device__ ull     g_mpk[NN];
__device__ int     g_order[NN];
__device__ int     g_scls[NN];
__device__ float   g_sx2[NN];
__device__ int     g_cstart[NC];
__device__ int     g_count[NC];
__device__ __half2 g_Eh[NN][64];

__device__ __forceinline__ uint32_t smem_u32(const void* p) {
    uint32_t a;
    asm("{ .reg .u64 t; cvta.to.shared.u64 t, %1; cvt.u32.u64 %0, t; }" : "=r"(a) : "l"(p));
    return a;
}

#define LDSM4(r0, r1, r2, r3, addr)                                          \
    asm volatile("ldmatrix.sync.aligned.m8n8.x4.shared.b16 {%0,%1,%2,%3},[%4];" \
        : "=r"(r0), "=r"(r1), "=r"(r2), "=r"(r3) : "r"(addr))

#define MMA16816(cp, a0, a1, a2, a3, b0, b1)                                 \
    asm volatile("mma.sync.aligned.m16n8k16.row.col.f32.f16.f16.f32 "        \
        "{%0,%1,%2,%3},{%4,%5,%6,%7},{%8,%9},{%0,%1,%2,%3};"                 \
        : "+f"((cp)[0]), "+f"((cp)[1]), "+f"((cp)[2]), "+f"((cp)[3])         \
        : "r"(a0), "r"(a1), "r"(a2), "r"(a3), "r"(b0), "r"(b1))

// ---------------------------------------------------------------------------
// Kernel 1: parallel stable (class,index) sort. 1 block, 1024 threads.
// ---------------------------------------------------------------------------
__global__ __launch_bounds__(1024)
void bh_table(const int* __restrict__ labels)
{
    __shared__ int wpre[32][NC];
    __shared__ int lofs[1024][NC];
    __shared__ int cst[NC];

    const int tid  = threadIdx.x;
    const int w    = tid >> 5;
    const int lane = tid & 31;
    const int base = tid * 8;

    int4 l0 = *reinterpret_cast<const int4*>(labels + base);
    int4 l1 = *reinterpret_cast<const int4*>(labels + base + 4);
    int lab[8] = {l0.x, l0.y, l0.z, l0.w, l1.x, l1.y, l1.z, l1.w};

    int lc[NC];
#pragma unroll
    for (int c = 0; c < NC; c++) lc[c] = 0;
#pragma unroll
    for (int i = 0; i < 8; i++)
#pragma unroll
        for (int c = 0; c < NC; c++) lc[c] += (lab[i] == c);

#pragma unroll
    for (int c = 0; c < NC; c++) {
        int v = lc[c], inc = v;
#pragma unroll
        for (int off = 1; off < 32; off <<= 1) {
            int o = __shfl_up_sync(0xffffffffu, inc, off);
            if (lane >= off) inc += o;
        }
        lofs[tid][c] = inc - v;
        if (lane == 31) wpre[w][c] = inc;
    }
    __syncthreads();

    if (tid < NC) {
        int run = 0;
        for (int t = 0; t < 32; t++) { int tmp = wpre[t][tid]; wpre[t][tid] = run; run += tmp; }
        g_count[tid] = run;
    }
    __syncthreads();
    if (tid == 0) {
        int run = 0;
        for (int c = 0; c < NC; c++) { cst[c] = run; g_cstart[c] = run; run += g_count[c]; }
    }
    __syncthreads();

#pragma unroll
    for (int i = 0; i < 8; i++) {
        int c = lab[i];
        int rk = 0;
#pragma unroll
        for (int j = 0; j < 8; j++) rk += (j < i) && (lab[j] == c);
        int pos = cst[c] + wpre[w][c] + lofs[tid][c] + rk;
        g_order[pos] = base + i;
        g_scls[pos]  = c;
    }
}

// ---------------------------------------------------------------------------
// Kernel 2: pack sorted rows to fp16, compute norms, zero stats + out.
// ---------------------------------------------------------------------------
__global__ void bh_pack(const float* __restrict__ E, float* __restrict__ out)
{
    const int p    = (blockIdx.x * blockDim.x + threadIdx.x) >> 5;
    const int lane = threadIdx.x & 31;
    if (blockIdx.x == 0 && threadIdx.x == 0) out[0] = 0.0f;

    const int gi = g_order[p];
    float4 v = *reinterpret_cast<const float4*>(E + (size_t)gi * DD + lane * 4);
    g_Eh[p][lane * 2]     = __floats2half2_rn(v.x, v.y);
    g_Eh[p][lane * 2 + 1] = __floats2half2_rn(v.z, v.w);

    float s = v.x * v.x + v.y * v.y + v.z * v.z + v.w * v.w;
#pragma unroll
    for (int off = 16; off >= 1; off >>= 1)
        s += __shfl_xor_sync(0xffffffffu, s, off);
    if (lane == 0) { g_x2[gi] = s; g_sx2[p] = s; g_mpk[p] = 0ull; }
    if (lane < NC) g_S[p][lane] = 0.f;
}

// ---------------------------------------------------------------------------
// Templated epilogue: SHARE = row/col class sets intersect (max tracking on).
// ---------------------------------------------------------------------------
template <bool SHARE>
__device__ __forceinline__ void tile_epilogue(
    float (&cfr)[2][8][4],
    int wr, int wc, int g, int t, int tid, bool diag,
    int rowbase, int jbase, int srow, int scol,
    int cAr, int cBr, int cAc, int cBc,
    const float* sxr, const float* sxj,
    __half2* dsh, float* qA, float* qB, float* qV, int* qR)
{
    int   rowt[2][2], rcv[2][2];
    float xrv[2][2], sA[2][2], sBv[2][2], mv[2][2];
    int   mc[2][2];
#pragma unroll
    for (int mi = 0; mi < 2; ++mi)
#pragma unroll
        for (int h = 0; h < 2; ++h) {
            rowt[mi][h] = wr * 32 + mi * 16 + g + h * 8;
            xrv[mi][h]  = sxr[rowt[mi][h]];
            rcv[mi][h]  = (rowt[mi][h] < srow) ? cAr : cBr;
            sA[mi][h] = 0.f; sBv[mi][h] = 0.f; mv[mi][h] = -1.f; mc[mi][h] = 0;
        }

#pragma unroll
    for (int n = 0; n < 8; ++n) {
        const int  c0  = wc * 64 + n * 8 + t * 2;
        const float xj0 = sxj[c0], xj1 = sxj[c0 + 1];
        const bool a0 = c0 < scol, a1 = (c0 + 1) < scol;
        const int  cc0 = a0 ? cAc : cBc, cc1 = a1 ? cAc : cBc;
#pragma unroll
        for (int mi = 0; mi < 2; ++mi)
#pragma unroll
            for (int h = 0; h < 2; ++h) {
                float d0 = fmaxf(fmaf(-2.0f, cfr[mi][n][h * 2],     xrv[mi][h] + xj0), 0.0f);
                float d1 = fmaxf(fmaf(-2.0f, cfr[mi][n][h * 2 + 1], xrv[mi][h] + xj1), 0.0f);
                if (a0) sA[mi][h] += d0; else sBv[mi][h] += d0;
                if (a1) sA[mi][h] += d1; else sBv[mi][h] += d1;
                if (SHARE) {
                    if (cc0 == rcv[mi][h] && d0 > mv[mi][h]) { mv[mi][h] = d0; mc[mi][h] = c0; }
                    if (cc1 == rcv[mi][h] && d1 > mv[mi][h]) { mv[mi][h] = d1; mc[mi][h] = c0 + 1; }
                }
                if (!diag)
                    dsh[rowt[mi][h] * DP2 + (c0 >> 1)] = __floats2half2_rn(d0, d1);
            }
    }

#pragma unroll
    for (int off = 2; off >= 1; off >>= 1) {
#pragma unroll
        for (int mi = 0; mi < 2; ++mi)
#pragma unroll
            for (int h = 0; h < 2; ++h) {
                sA[mi][h]  += __shfl_down_sync(0xffffffffu, sA[mi][h],  off, 4);
                sBv[mi][h] += __shfl_down_sync(0xffffffffu, sBv[mi][h], off, 4);
                if (SHARE) {
                    float ov = __shfl_down_sync(0xffffffffu, mv[mi][h], off, 4);
                    int   oc = __shfl_down_sync(0xffffffffu, mc[mi][h], off, 4);
                    if (ov > mv[mi][h]) { mv[mi][h] = ov; mc[mi][h] = oc; }
                }
            }
    }
    if (t == 0) {
#pragma unroll
        for (int mi = 0; mi < 2; ++mi)
#pragma unroll
            for (int h = 0; h < 2; ++h) {
                const int rp = rowbase + rowt[mi][h];
                atomicAdd(&g_S[rp][cAc], sA[mi][h]);
                if (scol < BT) atomicAdd(&g_S[rp][cBc], sBv[mi][h]);
                if (SHARE && mv[mi][h] >= 0.f)
                    atomicMax(&g_mpk[rp], (((ull)__float_as_uint(mv[mi][h])) << 32)
                                          | (unsigned)(jbase + mc[mi][h]));
            }
    }

    // ---- col pass over fp16 d (off-diagonal only) ----
    if (!diag) {
        __syncthreads();
        const int cp = tid & 63, q = tid >> 6;
        const int c0 = cp * 2, c1 = c0 + 1;
        const int cc0 = (c0 < scol) ? cAc : cBc;
        const int cc1 = (c1 < scol) ? cAc : cBc;
        float s0A = 0.f, s0B = 0.f, s1A = 0.f, s1B = 0.f;
        float m0 = -1.f, m1 = -1.f;
        int   r0 = 0, r1 = 0;
#pragma unroll 8
        for (int rr = 0; rr < 32; ++rr) {
            const int row = q * 32 + rr;
            float2 d = __half22float2(dsh[row * DP2 + cp]);
            const bool isA = row < srow;
            if (isA) { s0A += d.x; s1A += d.y; } else { s0B += d.x; s1B += d.y; }
            if (SHARE) {
                const int rc = isA ? cAr : cBr;
                if (rc == cc0 && d.x > m0) { m0 = d.x; r0 = row; }
                if (rc == cc1 && d.y > m1) { m1 = d.y; r1 = row; }
            }
        }
        qA[q * 128 + c0] = s0A;  qA[q * 128 + c1] = s1A;
        qB[q * 128 + c0] = s0B;  qB[q * 128 + c1] = s1B;
        if (SHARE) {
            qV[q * 128 + c0] = m0;   qV[q * 128 + c1] = m1;
            qR[q * 128 + c0] = r0;   qR[q * 128 + c1] = r1;
        }
        __syncthreads();

        if (tid < BT) {
            const int col = tid;
            float sAc = 0.f, sBc = 0.f, mvc = -1.f;
            int   mrc = 0;
#pragma unroll
            for (int qq = 0; qq < 4; ++qq) {
                sAc += qA[qq * 128 + col];
                sBc += qB[qq * 128 + col];
                if (SHARE) {
                    float v = qV[qq * 128 + col];
                    if (v > mvc) { mvc = v; mrc = qR[qq * 128 + col]; }
                }
            }
            const int cpo = jbase + col;
            atomicAdd(&g_S[cpo][cAr], sAc);
            if (srow < BT) atomicAdd(&g_S[cpo][cBr], sBc);
            if (SHARE && mvc >= 0.f)
                atomicMax(&g_mpk[cpo], (((ull)__float_as_uint(mvc)) << 32)
                                       | (unsigned)(rowbase + mrc));
        }
    }
}

// ---------------------------------------------------------------------------
// Kernel 3: symmetric-tile Gram via HMMA; off-diag tiles scheduled first,
// diag tiles in the tail; epilogue specialized on class-sharing.
// ---------------------------------------------------------------------------
__global__ __launch_bounds__(256, 2)
void bh_main()
{
    extern __shared__ char smraw[];
    const uint32_t sb = smem_u32(smraw);
    __half*  Ah  = (__half*)smraw;
    __half2* dsh = (__half2*)smraw;
    float*   qA  = (float*)(smraw + 128 * DP2 * 4);
    float*   qB  = qA + 512;
    float*   qV  = qB + 512;
    int*     qR  = (int*)(qV + 512);
    float*   sxj = (float*)(smraw + 69632);
    float*   sxr = sxj + 128;
    __shared__ int sb_col, sb_row;

    const int tid  = threadIdx.x;
    const int w    = tid >> 5;
    const int lane = tid & 31;
    const int g    = lane >> 2, t = lane & 3;
    const int wr   = w & 3, wc = w >> 2;

    // schedule decode: off-diag (bi<bj) first, then diag
    int bi, bj;
    const int id = (int)blockIdx.x;
    if (id < NOFF) {
        float bf = (float)id;
        bi = (int)(62.5f - sqrtf(fmaxf(62.5f * 62.5f - 2.0f * bf, 0.0f)));
        if (bi < 0) bi = 0;
        while ((bi + 1) * (2 * NB - 2 - bi) / 2 <= id) ++bi;
        while (bi * (2 * NB - 1 - bi) / 2 > id) --bi;
        bj = bi + 1 + (id - bi * (2 * NB - 1 - bi) / 2);
    } else {
        bi = bj = id - NOFF;
    }
    const bool diag = (bi == bj);
    const int rowbase = bi * BT;
    const int jbase   = bj * BT;

    if (tid == 0) { sb_col = BT; sb_row = BT; }
    __syncthreads();
    if (tid < BT - 1) {
        if (g_scls[jbase + tid + 1]   != g_scls[jbase + tid])   atomicMin(&sb_col, tid + 1);
        if (g_scls[rowbase + tid + 1] != g_scls[rowbase + tid]) atomicMin(&sb_row, tid + 1);
    }

    // ---- tile loads ----
#pragma unroll
    for (int it = 0; it < 8; ++it) {
        int idx = tid + it * 256;
        int row = idx >> 4, c = idx & 15;
        uint4 v = *reinterpret_cast<const uint4*>(
            reinterpret_cast<const char*>(&g_Eh[rowbase + row][0]) + c * 16);
        *reinterpret_cast<uint4*>(Ah + row * PITCH + c * 8) = v;
    }
    if (!diag) {
        __half* Bh = Ah + 128 * PITCH;
#pragma unroll
        for (int it = 0; it < 8; ++it) {
            int idx = tid + it * 256;
            int row = idx >> 4, c = idx & 15;
            uint4 v = *reinterpret_cast<const uint4*>(
                reinterpret_cast<const char*>(&g_Eh[jbase + row][0]) + c * 16);
            *reinterpret_cast<uint4*>(Bh + row * PITCH + c * 8) = v;
        }
    }
    if (tid < BT) { sxj[tid] = g_sx2[jbase + tid]; sxr[tid] = g_sx2[rowbase + tid]; }
    __syncthreads();

    // ---- MMA mainloop ----
    const uint32_t aBase0 = sb + ((wr * 32 + (lane & 15)) * PITCH + ((lane >> 4) << 3)) * 2;
    const uint32_t aBase1 = aBase0 + 16 * PITCH * 2;
    const uint32_t bTile  = diag ? sb : (sb + 128 * PITCH * 2);
    const uint32_t bBase  = bTile + ((wc * 64 + (lane & 7) + ((lane >> 4) << 3)) * PITCH
                                     + (((lane >> 3) & 1) << 3)) * 2;

    float cfr[2][8][4];
#pragma unroll
    for (int mi = 0; mi < 2; ++mi)
#pragma unroll
        for (int n = 0; n < 8; ++n)
#pragma unroll
            for (int q = 0; q < 4; ++q) cfr[mi][n][q] = 0.f;

#pragma unroll
    for (int ks = 0; ks < 8; ++ks) {
        uint32_t a00, a01, a02, a03, a10, a11, a12, a13;
        LDSM4(a00, a01, a02, a03, aBase0 + ks * 32);
        LDSM4(a10, a11, a12, a13, aBase1 + ks * 32);
#pragma unroll
        for (int np = 0; np < 4; ++np) {
            uint32_t b0, b1, b2, b3;
            LDSM4(b0, b1, b2, b3, bBase + np * (16 * PITCH * 2) + ks * 32);
            MMA16816(cfr[0][np * 2],     a00, a01, a02, a03, b0, b1);
            MMA16816(cfr[0][np * 2 + 1], a00, a01, a02, a03, b2, b3);
            MMA16816(cfr[1][np * 2],     a10, a11, a12, a13, b0, b1);
            MMA16816(cfr[1][np * 2 + 1], a10, a11, a12, a13, b2, b3);
        }
    }
    __syncthreads();

    const int scol = sb_col, srow = sb_row;
    const int cAc = g_scls[jbase],   cBc = g_scls[jbase + BT - 1];
    const int cAr = g_scls[rowbase], cBr = g_scls[rowbase + BT - 1];

    // class intervals intersect? (sorted order: cAr<=cBr, cAc<=cBc, bi<=bj)
    const bool share = (cAc <= cBr) && (cAr <= cBc);

    if (share)
        tile_epilogue<true >(cfr, wr, wc, g, t, tid, diag, rowbase, jbase,
                             srow, scol, cAr, cBr, cAc, cBc, sxr, sxj,
                             dsh, qA, qB, qV, qR);
    else
        tile_epilogue<false>(cfr, wr, wc, g, t, tid, diag, rowbase, jbase,
                             srow, scol, cAr, cBr, cAc, cBc, sxr, sxj,
                             dsh, qA, qB, qV, qR);
}

// ---------------------------------------------------------------------------
// Kernel 4: finalize — warp per sorted anchor: argmin, class walk,
// EXACT fp32 recompute of d_pos (tracked argmax) and d_neg.
// ---------------------------------------------------------------------------
__global__ void bh_final(const float* __restrict__ E, float* __restrict__ out)
{
    const int p    = (blockIdx.x * blockDim.x + threadIdx.x) >> 5;
    const int lane = threadIdx.x & 31;

    float T = 0.f, S[NC];
#pragma unroll
    for (int c = 0; c < NC; c++) { S[c] = g_S[p][c]; T += S[c]; }

    float best = 3.4e38f;
    int   ks   = 0;
#pragma unroll
    for (int c = 0; c < NC; c++) {
        float nd = T - S[c];
        if (nd < best) { best = nd; ks = c; }
    }

    const int la = g_scls[p];
    int rem = ks, js = 0;
#pragma unroll
    for (int c = 0; c < NC; c++) {
        if (c == la) continue;
        int cn = g_count[c];
        if (rem < cn) { js = g_order[g_cstart[c] + rem]; rem = 0x7fffffff; }
        else rem -= cn;
    }

    const ull key = g_mpk[p];
    const int jpq = (int)(key & 0xffffffffu);
    const int gjp = g_order[jpq];
    const int gi  = g_order[p];

    float4 a  = *reinterpret_cast<const float4*>(E + (size_t)gi  * DD + lane * 4);
    float4 bp = *reinterpret_cast<const float4*>(E + (size_t)gjp * DD + lane * 4);
    float4 bn = *reinterpret_cast<const float4*>(E + (size_t)js  * DD + lane * 4);
    float dotp = a.x * bp.x + a.y * bp.y + a.z * bp.z + a.w * bp.w;
    float dotn = a.x * bn.x + a.y * bn.y + a.z * bn.z + a.w * bn.w;
#pragma unroll
    for (int off = 16; off >= 1; off >>= 1) {
        dotp += __shfl_xor_sync(0xffffffffu, dotp, off);
        dotn += __shfl_xor_sync(0xffffffffu, dotn, off);
    }

    float loss = 0.f;
    if (lane == 0) {
        float dp = fmaxf(g_x2[gi] + g_x2[gjp] - 2.0f * dotp, 0.0f);
        float dn = fmaxf(g_x2[gi] + g_x2[js]  - 2.0f * dotn, 0.0f);
        loss = fmaxf(dp - dn + 1.0f, 0.0f);
    }

    __shared__ float wsum[8];
    if (lane == 0) wsum[threadIdx.x >> 5] = loss;
    __syncthreads();
    if (threadIdx.x == 0) {
        float s = 0.f;
#pragma unroll
        for (int w = 0; w < 8; w++) s += wsum[w];
        atomicAdd(out, s * (1.0f / NN));
    }
}

// ---------------------------------------------------------------------------
extern "C" void kernel_launch(void* const* d_in, const int* in_sizes, int n_in,
                              void* d_out, int out_size)
{
    const float* E      = (const float*)d_in[0];
    const int*   labels = (const int*)d_in[1];
    float*       out    = (float*)d_out;

    const int smem = 69632 + 2 * 128 * 4;
    cudaFuncSetAttribute(bh_main, cudaFuncAttributeMaxDynamicSharedMemorySize, smem);

    bh_table<<<1, 1024>>>(labels);
    bh_pack<<<NN * 32 / 256, 256>>>(E, out);
    bh_main<<<NTILES, 256, smem>>>();
    bh_final<<<NN * 32 / 256, 256>>>(E, out);
}